// round 1
// baseline (speedup 1.0000x reference)
#include <cuda_runtime.h>
#include <math.h>

// Problem constants
#define B_   512
#define L_   64
#define H_   16
#define DH_  64
#define D_   1024
#define M_   (B_ * L_)        // 32768 rows

// ---------------------------------------------------------------------------
// Scratch (static __device__ arrays — no allocations allowed)
// ---------------------------------------------------------------------------
__device__ float g_q[(size_t)B_ * H_ * L_ * DH_];    // [B,H,L,Dh]
__device__ float g_k[(size_t)B_ * H_ * L_ * DH_];
__device__ float g_v[(size_t)B_ * H_ * L_ * DH_];
__device__ float g_att[(size_t)M_ * D_];             // [B*L, H*Dh]

// ---------------------------------------------------------------------------
// Tiled fp32 GEMM: C[M,1024] = A[M,1024] @ W[1024,1024]
// remap=1: write C into [B,H,L,Dh] layout (for Q/K/V); remap=0: row-major.
// BM=BN=128, BK=16, 256 threads, 8x8 per thread.
// ---------------------------------------------------------------------------
#define BM 128
#define BN 128
#define BK 16

__global__ __launch_bounds__(256) void gemm_kernel(
    const float* __restrict__ A, const float* __restrict__ W,
    float* __restrict__ C, int remap)
{
    __shared__ float As[BK][BM + 4];   // [16][132] transposed A tile
    __shared__ float Bs[BK][BN];       // [16][128]

    const int tid = threadIdx.x;
    const int tx = tid & 15;           // 0..15 -> n
    const int ty = tid >> 4;           // 0..15 -> m
    const int bn = blockIdx.x;
    const int bm = blockIdx.y;

    const float* Ag = A + (size_t)(bm * BM) * D_;
    const float* Wg = W + bn * BN;

    float acc[8][8];
#pragma unroll
    for (int i = 0; i < 8; i++)
#pragma unroll
        for (int j = 0; j < 8; j++) acc[i][j] = 0.0f;

    for (int k0 = 0; k0 < D_; k0 += BK) {
        // Load A tile (128 x 16) as float4, store transposed into As[k][m]
#pragma unroll
        for (int it = 0; it < 2; it++) {
            int idx = it * 256 + tid;          // 0..511
            int r  = idx >> 2;                 // row in tile 0..127
            int c4 = idx & 3;                  // which float4 of the 16 k's
            float4 va = *(const float4*)(Ag + (size_t)r * D_ + k0 + c4 * 4);
            As[c4 * 4 + 0][r] = va.x;
            As[c4 * 4 + 1][r] = va.y;
            As[c4 * 4 + 2][r] = va.z;
            As[c4 * 4 + 3][r] = va.w;
        }
        // Load B tile (16 x 128) as float4
#pragma unroll
        for (int it = 0; it < 2; it++) {
            int idx = it * 256 + tid;          // 0..511
            int r = idx >> 5;                  // k row 0..15
            int c = idx & 31;                  // float4 col 0..31
            float4 vb = *(const float4*)(Wg + (size_t)(k0 + r) * D_ + c * 4);
            *(float4*)(&Bs[r][c * 4]) = vb;
        }
        __syncthreads();

#pragma unroll
        for (int kk = 0; kk < BK; kk++) {
            float4 a0 = *(const float4*)(&As[kk][ty * 8]);
            float4 a1 = *(const float4*)(&As[kk][ty * 8 + 4]);
            float4 b0 = *(const float4*)(&Bs[kk][tx * 8]);
            float4 b1 = *(const float4*)(&Bs[kk][tx * 8 + 4]);
            float a[8] = {a0.x, a0.y, a0.z, a0.w, a1.x, a1.y, a1.z, a1.w};
            float b[8] = {b0.x, b0.y, b0.z, b0.w, b1.x, b1.y, b1.z, b1.w};
#pragma unroll
            for (int i = 0; i < 8; i++)
#pragma unroll
                for (int j = 0; j < 8; j++) acc[i][j] = fmaf(a[i], b[j], acc[i][j]);
        }
        __syncthreads();
    }

    const int mb = bm * BM + ty * 8;
    const int nb = bn * BN + tx * 8;

    if (remap == 0) {
#pragma unroll
        for (int i = 0; i < 8; i++) {
            float4 v0 = make_float4(acc[i][0], acc[i][1], acc[i][2], acc[i][3]);
            float4 v1 = make_float4(acc[i][4], acc[i][5], acc[i][6], acc[i][7]);
            *(float4*)(&C[(size_t)(mb + i) * D_ + nb])     = v0;
            *(float4*)(&C[(size_t)(mb + i) * D_ + nb + 4]) = v1;
        }
    } else {
        // n -> (h, dh); m -> (b, l); write [B,H,L,Dh]
        const int h  = nb >> 6;
        const int dh = nb & 63;
#pragma unroll
        for (int i = 0; i < 8; i++) {
            int m = mb + i;
            int b = m >> 6;
            int l = m & 63;
            size_t dst = (((size_t)(b * H_ + h) * L_) + l) * DH_ + dh;
            float4 v0 = make_float4(acc[i][0], acc[i][1], acc[i][2], acc[i][3]);
            float4 v1 = make_float4(acc[i][4], acc[i][5], acc[i][6], acc[i][7]);
            *(float4*)(&C[dst])     = v0;
            *(float4*)(&C[dst + 4]) = v1;
        }
    }
}

// ---------------------------------------------------------------------------
// Attention: one block per (b,h). L=Dh=64. 256 threads.
// Phase 1: thread (q=tid/4, tk=tid%4) computes 16 logits (keys tk + 4*kk),
//          softmax via shfl across the 4-thread group.
// Phase 2: thread (q=tid/4, dr=tid%4) computes out[q][dr*16 .. +15].
// Output written as [B, L, H*Dh] so the final GEMM is plain row-major.
// ---------------------------------------------------------------------------
#define PAD 68   // 64+4 floats per row; keeps float4 alignment (68*4 % 16 == 0)

__global__ __launch_bounds__(256) void attn_kernel(
    const float* __restrict__ gq, const float* __restrict__ gk,
    const float* __restrict__ gv, const float* __restrict__ gbias,
    float* __restrict__ gout)
{
    extern __shared__ float sm[];
    float* qs = sm;                 // [64][PAD]
    float* ks = sm + 64 * PAD;      // [64][PAD]
    float* vs = sm + 2 * 64 * PAD;  // [64][PAD]
    float* ws = qs;                 // alias: reused for softmax weights

    const int tid = threadIdx.x;
    const int bh  = blockIdx.x;
    const int b   = bh >> 4;
    const int h   = bh & 15;
    const size_t base = (size_t)bh * (L_ * DH_);

    // Load Q, K, V tiles (64x64 each) with float4
#pragma unroll
    for (int i = 0; i < 4; i++) {
        int e   = i * 256 + tid;        // 0..1023 float4 slots
        int row = e >> 4;               // 0..63
        int c4  = e & 15;               // 0..15
        float4 vq = *(const float4*)(gq + base + row * 64 + c4 * 4);
        float4 vk = *(const float4*)(gk + base + row * 64 + c4 * 4);
        float4 vv = *(const float4*)(gv + base + row * 64 + c4 * 4);
        *(float4*)(qs + row * PAD + c4 * 4) = vq;
        *(float4*)(ks + row * PAD + c4 * 4) = vk;
        *(float4*)(vs + row * PAD + c4 * 4) = vv;
    }
    __syncthreads();

    const int q  = tid >> 2;
    const int tk = tid & 3;

    // Hoist this thread's query row into registers
    float4 qreg[16];
#pragma unroll
    for (int d4 = 0; d4 < 16; d4++)
        qreg[d4] = *(const float4*)(qs + q * PAD + d4 * 4);

    // Logits for keys {tk, tk+4, ..., tk+60}
    float lg[16];
    const float* bptr = gbias + (size_t)h * (L_ * L_) + q * L_;
#pragma unroll
    for (int kk = 0; kk < 16; kk++) {
        int key = kk * 4 + tk;
        float dot = 0.0f;
#pragma unroll
        for (int d4 = 0; d4 < 16; d4++) {
            float4 kb = *(const float4*)(ks + key * PAD + d4 * 4);
            dot = fmaf(qreg[d4].x, kb.x, dot);
            dot = fmaf(qreg[d4].y, kb.y, dot);
            dot = fmaf(qreg[d4].z, kb.z, dot);
            dot = fmaf(qreg[d4].w, kb.w, dot);
        }
        lg[kk] = dot * 0.125f + bptr[key];
    }

    // Softmax across 64 keys (16 local + butterfly across the 4-thread group)
    float mx = lg[0];
#pragma unroll
    for (int kk = 1; kk < 16; kk++) mx = fmaxf(mx, lg[kk]);
    mx = fmaxf(mx, __shfl_xor_sync(0xffffffffu, mx, 1));
    mx = fmaxf(mx, __shfl_xor_sync(0xffffffffu, mx, 2));

    float s = 0.0f;
#pragma unroll
    for (int kk = 0; kk < 16; kk++) { lg[kk] = expf(lg[kk] - mx); s += lg[kk]; }
    s += __shfl_xor_sync(0xffffffffu, s, 1);
    s += __shfl_xor_sync(0xffffffffu, s, 2);
    const float inv = 1.0f / s;

    __syncthreads();   // everyone done reading qs before aliasing as ws

    // Store unnormalized weights: ws[q][key]
#pragma unroll
    for (int kk = 0; kk < 16; kk++)
        ws[q * PAD + (kk * 4 + tk)] = lg[kk];
    __syncthreads();

    // Phase 2: out[q][d], d in [dr*16, dr*16+16)
    const int dr = tk;
    float acc[16];
#pragma unroll
    for (int j = 0; j < 16; j++) acc[j] = 0.0f;

    for (int key = 0; key < 64; key++) {
        float w = ws[q * PAD + key];
#pragma unroll
        for (int j4 = 0; j4 < 4; j4++) {
            float4 vv = *(const float4*)(vs + key * PAD + dr * 16 + j4 * 4);
            acc[j4 * 4 + 0] = fmaf(w, vv.x, acc[j4 * 4 + 0]);
            acc[j4 * 4 + 1] = fmaf(w, vv.y, acc[j4 * 4 + 1]);
            acc[j4 * 4 + 2] = fmaf(w, vv.z, acc[j4 * 4 + 2]);
            acc[j4 * 4 + 3] = fmaf(w, vv.w, acc[j4 * 4 + 3]);
        }
    }

    float* op = gout + ((size_t)(b * L_ + q)) * D_ + h * DH_ + dr * 16;
#pragma unroll
    for (int j4 = 0; j4 < 4; j4++) {
        float4 r = make_float4(acc[j4 * 4 + 0] * inv, acc[j4 * 4 + 1] * inv,
                               acc[j4 * 4 + 2] * inv, acc[j4 * 4 + 3] * inv);
        *(float4*)(op + j4 * 4) = r;
    }
}

// ---------------------------------------------------------------------------
// Launch
// ---------------------------------------------------------------------------
extern "C" void kernel_launch(void* const* d_in, const int* in_sizes, int n_in,
                              void* d_out, int out_size)
{
    const float* x    = (const float*)d_in[0];
    const float* bias = (const float*)d_in[1];
    const float* Wq   = (const float*)d_in[2];
    const float* Wk   = (const float*)d_in[3];
    const float* Wv   = (const float*)d_in[4];
    const float* Wo   = (const float*)d_in[5];
    float* out = (float*)d_out;

    void *pq, *pk, *pv, *pa;
    cudaGetSymbolAddress(&pq, g_q);
    cudaGetSymbolAddress(&pk, g_k);
    cudaGetSymbolAddress(&pv, g_v);
    cudaGetSymbolAddress(&pa, g_att);

    dim3 grid(D_ / BN, M_ / BM);   // (8, 256)

    gemm_kernel<<<grid, 256>>>(x, Wq, (float*)pq, 1);
    gemm_kernel<<<grid, 256>>>(x, Wk, (float*)pk, 1);
    gemm_kernel<<<grid, 256>>>(x, Wv, (float*)pv, 1);

    const int smem = 3 * 64 * PAD * (int)sizeof(float);   // 52224 B
    cudaFuncSetAttribute(attn_kernel, cudaFuncAttributeMaxDynamicSharedMemorySize, smem);
    attn_kernel<<<B_ * H_, 256, smem>>>((const float*)pq, (const float*)pk,
                                        (const float*)pv, bias, (float*)pa);

    gemm_kernel<<<grid, 256>>>((const float*)pa, Wo, out, 0);
}

// round 5
// speedup vs baseline: 3.1007x; 3.1007x over previous
#include <cuda_runtime.h>
#include <cuda_fp16.h>
#include <cstdint>
#include <math.h>

// Problem constants
#define B_   512
#define L_   64
#define H_   16
#define DH_  64
#define D_   1024
#define M_   (B_ * L_)        // 32768
#define K2_  2048             // split K (hi/lo interleaved)
#define NT_  (K2_ / 64)       // 32 K-tiles of 64 halfs

// ---------------------------------------------------------------------------
// Scratch (__device__ globals — no allocations allowed)
// ---------------------------------------------------------------------------
__device__ __half g_xs [(size_t)M_ * K2_];    // x split     [M, 2K]
__device__ __half g_ats[(size_t)M_ * K2_];    // attn split  [M, 2K]
__device__ __half g_wq [(size_t)D_ * K2_];    // Wq^T split  [N, 2K]
__device__ __half g_wk [(size_t)D_ * K2_];
__device__ __half g_wv [(size_t)D_ * K2_];
__device__ __half g_wo [(size_t)D_ * K2_];
__device__ float g_q[(size_t)B_ * H_ * L_ * DH_];    // [B,H,L,Dh] fp32
__device__ float g_k[(size_t)B_ * H_ * L_ * DH_];
__device__ float g_v[(size_t)B_ * H_ * L_ * DH_];

// ---------------------------------------------------------------------------
// fp32 -> (hi,lo) fp16 split (interleaved in K)
// ---------------------------------------------------------------------------
__device__ __forceinline__ __half2 split1(float v) {
    __half hi = __float2half_rn(v);
    __half lo = __float2half_rn(v - __half2float(hi));
    __half2 p; p.x = hi; p.y = lo; return p;
}

__global__ __launch_bounds__(256) void split_rows(
    const float* __restrict__ in, __half* __restrict__ out, int n4)
{
    int i = blockIdx.x * blockDim.x + threadIdx.x;
    if (i >= n4) return;
    float4 v = ((const float4*)in)[i];
    union { uint4 u; __half2 p[4]; } pk;
    pk.p[0] = split1(v.x); pk.p[1] = split1(v.y);
    pk.p[2] = split1(v.z); pk.p[3] = split1(v.w);
    ((uint4*)out)[i] = pk.u;
}

// W[1024,1024] -> Wt_split[n][2k] (transpose + split)
__global__ __launch_bounds__(256) void split_w_t(
    const float* __restrict__ W, __half* __restrict__ Wt)
{
    __shared__ float t[32][33];
    const int bn = blockIdx.x, bk = blockIdx.y;
    const int tx = threadIdx.x, ty = threadIdx.y;   // 32 x 8
#pragma unroll
    for (int i = 0; i < 32; i += 8)
        t[ty + i][tx] = W[(size_t)(bk * 32 + ty + i) * D_ + bn * 32 + tx];
    __syncthreads();
    __half2* Wt2 = (__half2*)Wt;
#pragma unroll
    for (int i = 0; i < 32; i += 8) {
        int n = bn * 32 + ty + i;
        int k = bk * 32 + tx;
        Wt2[(size_t)n * 1024 + k] = split1(t[tx][ty + i]);
    }
}

// ---------------------------------------------------------------------------
// HMMA GEMM: C[M,1024] f32 = A[M,2048]h . Bt[1024,2048]h ^T
// 128x128 tile, BK=64 halfs, cp.async double buffer, 8 warps (2m x 4n),
// warp tile 64x32, mma.sync.m16n8k16.
// remap=1: scatter to [B,H,L,Dh]; remap=0: row-major.
// ---------------------------------------------------------------------------
#define STAGE_BYTES 32768          // A(16K) + B(16K)
#define SMEM_B_OFF  16384

__device__ __forceinline__ uint32_t smem_u32(const void* p) {
    uint32_t a;
    asm("{ .reg .u64 t; cvta.to.shared.u64 t, %1; cvt.u32.u64 %0, t; }"
        : "=r"(a) : "l"(p));
    return a;
}

__device__ __forceinline__ void cp16(uint32_t dst, const void* src) {
    asm volatile("cp.async.cg.shared.global [%0], [%1], 16;\n"
                 :: "r"(dst), "l"(src));
}

__global__ __launch_bounds__(256) void gemm_tc(
    const __half* __restrict__ A,
    const __half* __restrict__ Bt,
    float* __restrict__ C, int remap)
{
    extern __shared__ char smem[];
    const uint32_t sbase = smem_u32(smem);
    const int tid = threadIdx.x;
    const int wid = tid >> 5;
    const int lid = tid & 31;
    const int wm  = wid >> 2;          // 0..1  (64 rows)
    const int wn  = wid & 3;           // 0..3  (32 cols)
    const int nb = blockIdx.x;         // 0..7
    const int mb = blockIdx.y;         // 0..255

    const __half* Ab = A  + (size_t)(mb * 128) * K2_;
    const __half* Bb = Bt + (size_t)(nb * 128) * K2_;

    // per-thread load pattern: 4 chunks per operand per stage
    uint32_t soff[4]; int lr[4], lc[4];
#pragma unroll
    for (int i = 0; i < 4; i++) {
        int idx = i * 256 + tid;
        int r = idx >> 3, c = idx & 7;
        lr[i] = r; lc[i] = c;
        soff[i] = (uint32_t)(r * 128 + (c ^ (r & 7)) * 16);
    }

    float acc[4][4][4];
#pragma unroll
    for (int mi = 0; mi < 4; mi++)
#pragma unroll
        for (int ni = 0; ni < 4; ni++)
#pragma unroll
            for (int e = 0; e < 4; e++) acc[mi][ni][e] = 0.0f;

    const int a_row = wm * 64 + (lid & 15);
    const int a_kh  = lid >> 4;
    const int b_row = wn * 32 + ((lid >> 4) * 8) + (lid & 7);
    const int b_kh  = (lid >> 3) & 1;

    // prologue: stage 0
#pragma unroll
    for (int i = 0; i < 4; i++) {
        cp16(sbase + soff[i],              Ab + (size_t)lr[i] * K2_ + lc[i] * 8);
        cp16(sbase + SMEM_B_OFF + soff[i], Bb + (size_t)lr[i] * K2_ + lc[i] * 8);
    }
    asm volatile("cp.async.commit_group;\n");

    for (int it = 0; it < NT_; ++it) {
        if (it + 1 < NT_) {
            const uint32_t st = sbase + ((it + 1) & 1) * STAGE_BYTES;
            const int k0 = (it + 1) * 64;
#pragma unroll
            for (int i = 0; i < 4; i++) {
                cp16(st + soff[i],              Ab + (size_t)lr[i] * K2_ + k0 + lc[i] * 8);
                cp16(st + SMEM_B_OFF + soff[i], Bb + (size_t)lr[i] * K2_ + k0 + lc[i] * 8);
            }
            asm volatile("cp.async.commit_group;\n");
            asm volatile("cp.async.wait_group 1;\n");
        } else {
            asm volatile("cp.async.wait_group 0;\n");
        }
        __syncthreads();

        const uint32_t sa = sbase + (it & 1) * STAGE_BYTES;
        const uint32_t sb = sa + SMEM_B_OFF;

#pragma unroll
        for (int k16 = 0; k16 < 4; k16++) {
            uint32_t af[4][4];
#pragma unroll
            for (int mi = 0; mi < 4; mi++) {
                int row = a_row + mi * 16;
                int ch  = (k16 * 2 + a_kh) ^ (row & 7);
                uint32_t ad = sa + row * 128 + ch * 16;
                asm volatile(
                    "ldmatrix.sync.aligned.m8n8.x4.shared.b16 {%0,%1,%2,%3}, [%4];"
                    : "=r"(af[mi][0]), "=r"(af[mi][1]), "=r"(af[mi][2]), "=r"(af[mi][3])
                    : "r"(ad));
            }
            uint32_t bf[4][2];
#pragma unroll
            for (int nj = 0; nj < 2; nj++) {
                int row = b_row + nj * 16;
                int ch  = (k16 * 2 + b_kh) ^ (row & 7);
                uint32_t bd = sb + row * 128 + ch * 16;
                uint32_t r0, r1, r2, r3;
                asm volatile(
                    "ldmatrix.sync.aligned.m8n8.x4.shared.b16 {%0,%1,%2,%3}, [%4];"
                    : "=r"(r0), "=r"(r1), "=r"(r2), "=r"(r3)
                    : "r"(bd));
                bf[nj * 2 + 0][0] = r0; bf[nj * 2 + 0][1] = r1;
                bf[nj * 2 + 1][0] = r2; bf[nj * 2 + 1][1] = r3;
            }
#pragma unroll
            for (int mi = 0; mi < 4; mi++)
#pragma unroll
                for (int ni = 0; ni < 4; ni++) {
                    asm volatile(
                        "mma.sync.aligned.m16n8k16.row.col.f32.f16.f16.f32 "
                        "{%0,%1,%2,%3}, {%4,%5,%6,%7}, {%8,%9}, {%0,%1,%2,%3};"
                        : "+f"(acc[mi][ni][0]), "+f"(acc[mi][ni][1]),
                          "+f"(acc[mi][ni][2]), "+f"(acc[mi][ni][3])
                        : "r"(af[mi][0]), "r"(af[mi][1]), "r"(af[mi][2]), "r"(af[mi][3]),
                          "r"(bf[ni][0]), "r"(bf[ni][1]));
                }
        }
        __syncthreads();
    }

    // Epilogue
    const int tq = lid >> 2;           // 0..7
    const int tr = lid & 3;            // 0..3
#pragma unroll
    for (int mi = 0; mi < 4; mi++) {
#pragma unroll
        for (int half_ = 0; half_ < 2; half_++) {
            int m = mb * 128 + wm * 64 + mi * 16 + tq + half_ * 8;
#pragma unroll
            for (int ni = 0; ni < 4; ni++) {
                int n = nb * 128 + wn * 32 + ni * 8 + tr * 2;
                float2 v;
                v.x = acc[mi][ni][half_ * 2 + 0];
                v.y = acc[mi][ni][half_ * 2 + 1];
                if (remap == 0) {
                    *(float2*)(C + (size_t)m * D_ + n) = v;
                } else {
                    int bb = m >> 6, ll = m & 63;
                    int h  = n >> 6, dh = n & 63;
                    *(float2*)(C + (((size_t)(bb * H_ + h) * L_ + ll) * DH_ + dh)) = v;
                }
            }
        }
    }
}

// ---------------------------------------------------------------------------
// Attention: one block per (b,h). Emits fp16 hi/lo split into g_ats [M, 2048].
// ---------------------------------------------------------------------------
#define PAD 68

__global__ __launch_bounds__(256) void attn_kernel(
    const float* __restrict__ gq, const float* __restrict__ gk,
    const float* __restrict__ gv, const float* __restrict__ gbias,
    __half* __restrict__ gout)
{
    extern __shared__ float sm[];
    float* qs = sm;
    float* ks = sm + 64 * PAD;
    float* vs = sm + 2 * 64 * PAD;
    float* ws = qs;

    const int tid = threadIdx.x;
    const int bh  = blockIdx.x;
    const int b   = bh >> 4;
    const int h   = bh & 15;
    const size_t base = (size_t)bh * (L_ * DH_);

#pragma unroll
    for (int i = 0; i < 4; i++) {
        int e   = i * 256 + tid;
        int row = e >> 4;
        int c4  = e & 15;
        float4 vq = *(const float4*)(gq + base + row * 64 + c4 * 4);
        float4 vk = *(const float4*)(gk + base + row * 64 + c4 * 4);
        float4 vv = *(const float4*)(gv + base + row * 64 + c4 * 4);
        *(float4*)(qs + row * PAD + c4 * 4) = vq;
        *(float4*)(ks + row * PAD + c4 * 4) = vk;
        *(float4*)(vs + row * PAD + c4 * 4) = vv;
    }
    __syncthreads();

    const int q  = tid >> 2;
    const int tk = tid & 3;

    float4 qreg[16];
#pragma unroll
    for (int d4 = 0; d4 < 16; d4++)
        qreg[d4] = *(const float4*)(qs + q * PAD + d4 * 4);

    float lg[16];
    const float* bptr = gbias + (size_t)h * (L_ * L_) + q * L_;
#pragma unroll
    for (int kk = 0; kk < 16; kk++) {
        int key = kk * 4 + tk;
        float dot = 0.0f;
#pragma unroll
        for (int d4 = 0; d4 < 16; d4++) {
            float4 kb = *(const float4*)(ks + key * PAD + d4 * 4);
            dot = fmaf(qreg[d4].x, kb.x, dot);
            dot = fmaf(qreg[d4].y, kb.y, dot);
            dot = fmaf(qreg[d4].z, kb.z, dot);
            dot = fmaf(qreg[d4].w, kb.w, dot);
        }
        lg[kk] = dot * 0.125f + bptr[key];
    }

    float mx = lg[0];
#pragma unroll
    for (int kk = 1; kk < 16; kk++) mx = fmaxf(mx, lg[kk]);
    mx = fmaxf(mx, __shfl_xor_sync(0xffffffffu, mx, 1));
    mx = fmaxf(mx, __shfl_xor_sync(0xffffffffu, mx, 2));

    float s = 0.0f;
#pragma unroll
    for (int kk = 0; kk < 16; kk++) { lg[kk] = expf(lg[kk] - mx); s += lg[kk]; }
    s += __shfl_xor_sync(0xffffffffu, s, 1);
    s += __shfl_xor_sync(0xffffffffu, s, 2);
    const float inv = 1.0f / s;

    __syncthreads();
#pragma unroll
    for (int kk = 0; kk < 16; kk++)
        ws[q * PAD + (kk * 4 + tk)] = lg[kk];
    __syncthreads();

    const int dr = tk;
    float acc[16];
#pragma unroll
    for (int j = 0; j < 16; j++) acc[j] = 0.0f;

    for (int key = 0; key < 64; key++) {
        float w = ws[q * PAD + key];
#pragma unroll
        for (int j4 = 0; j4 < 4; j4++) {
            float4 vv = *(const float4*)(vs + key * PAD + dr * 16 + j4 * 4);
            acc[j4 * 4 + 0] = fmaf(w, vv.x, acc[j4 * 4 + 0]);
            acc[j4 * 4 + 1] = fmaf(w, vv.y, acc[j4 * 4 + 1]);
            acc[j4 * 4 + 2] = fmaf(w, vv.z, acc[j4 * 4 + 2]);
            acc[j4 * 4 + 3] = fmaf(w, vv.w, acc[j4 * 4 + 3]);
        }
    }

    __half2* op = (__half2*)gout +
        ((size_t)(b * L_ + q)) * 1024 + (h * DH_ + dr * 16);
#pragma unroll
    for (int j4 = 0; j4 < 4; j4++) {
        union { uint4 u; __half2 p[4]; } pk;
#pragma unroll
        for (int e = 0; e < 4; e++)
            pk.p[e] = split1(acc[j4 * 4 + e] * inv);
        *(uint4*)(op + j4 * 4) = pk.u;
    }
}

// ---------------------------------------------------------------------------
// Launch
// ---------------------------------------------------------------------------
extern "C" void kernel_launch(void* const* d_in, const int* in_sizes, int n_in,
                              void* d_out, int out_size)
{
    const float* x    = (const float*)d_in[0];
    const float* bias = (const float*)d_in[1];
    const float* Wq   = (const float*)d_in[2];
    const float* Wk   = (const float*)d_in[3];
    const float* Wv   = (const float*)d_in[4];
    const float* Wo   = (const float*)d_in[5];
    float* out = (float*)d_out;

    void *pxs, *pats, *pwq, *pwk, *pwv, *pwo, *pq, *pk, *pv;
    cudaGetSymbolAddress(&pxs,  g_xs);
    cudaGetSymbolAddress(&pats, g_ats);
    cudaGetSymbolAddress(&pwq,  g_wq);
    cudaGetSymbolAddress(&pwk,  g_wk);
    cudaGetSymbolAddress(&pwv,  g_wv);
    cudaGetSymbolAddress(&pwo,  g_wo);
    cudaGetSymbolAddress(&pq,   g_q);
    cudaGetSymbolAddress(&pk,   g_k);
    cudaGetSymbolAddress(&pv,   g_v);

    // 1. split inputs
    split_rows<<<(M_ * D_ / 4 + 255) / 256, 256>>>(x, (__half*)pxs, M_ * D_ / 4);
    dim3 wt_threads(32, 8), wt_grid(32, 32);
    split_w_t<<<wt_grid, wt_threads>>>(Wq, (__half*)pwq);
    split_w_t<<<wt_grid, wt_threads>>>(Wk, (__half*)pwk);
    split_w_t<<<wt_grid, wt_threads>>>(Wv, (__half*)pwv);
    split_w_t<<<wt_grid, wt_threads>>>(Wo, (__half*)pwo);

    // 2. QKV projections on HMMA
    const int smem_gemm = 2 * STAGE_BYTES;   // 64 KB
    cudaFuncSetAttribute(gemm_tc, cudaFuncAttributeMaxDynamicSharedMemorySize, smem_gemm);
    dim3 gg(D_ / 128, M_ / 128);   // (8, 256)
    gemm_tc<<<gg, 256, smem_gemm>>>((const __half*)pxs, (const __half*)pwq, (float*)pq, 1);
    gemm_tc<<<gg, 256, smem_gemm>>>((const __half*)pxs, (const __half*)pwk, (float*)pk, 1);
    gemm_tc<<<gg, 256, smem_gemm>>>((const __half*)pxs, (const __half*)pwv, (float*)pv, 1);

    // 3. attention (emits fp16 split)
    const int smem_attn = 3 * 64 * PAD * (int)sizeof(float);
    cudaFuncSetAttribute(attn_kernel, cudaFuncAttributeMaxDynamicSharedMemorySize, smem_attn);
    attn_kernel<<<B_ * H_, 256, smem_attn>>>((const float*)pq, (const float*)pk,
                                             (const float*)pv, bias, (__half*)pats);

    // 4. output projection
    gemm_tc<<<gg, 256, smem_gemm>>>((const __half*)pats, (const __half*)pwo, out, 0);
}

// round 7
// speedup vs baseline: 4.3527x; 1.4038x over previous
#include <cuda_runtime.h>
#include <cuda_fp16.h>
#include <cstdint>
#include <math.h>

// Problem constants
#define B_   512
#define L_   64
#define H_   16
#define DH_  64
#define D_   1024
#define M_   (B_ * L_)        // 32768
#define K2_  2048             // split K (hi/lo interleaved)
#define NT_  (K2_ / 64)       // 32 K-tiles of 64 halfs

// ---------------------------------------------------------------------------
// Scratch (__device__ globals — no allocations allowed)
// ---------------------------------------------------------------------------
__device__ __half g_xs [(size_t)M_ * K2_];    // x split     [M, 2K]
__device__ __half g_ats[(size_t)M_ * K2_];    // attn split  [M, 2K]
__device__ __half g_wq [(size_t)D_ * K2_];    // Wq^T split  [N, 2K]
__device__ __half g_wk [(size_t)D_ * K2_];
__device__ __half g_wv [(size_t)D_ * K2_];
__device__ __half g_wo [(size_t)D_ * K2_];
__device__ float g_q[(size_t)B_ * H_ * L_ * DH_];    // [B,H,L,Dh] fp32
__device__ float g_k[(size_t)B_ * H_ * L_ * DH_];
__device__ float g_v[(size_t)B_ * H_ * L_ * DH_];

// ---------------------------------------------------------------------------
// fp32 -> (hi,lo) fp16 split
// ---------------------------------------------------------------------------
__device__ __forceinline__ __half2 split1(float v) {
    __half hi = __float2half_rn(v);
    __half lo = __float2half_rn(v - __half2float(hi));
    __half2 p; p.x = hi; p.y = lo; return p;
}

__global__ __launch_bounds__(256) void split_rows(
    const float* __restrict__ in, __half* __restrict__ out, int n4)
{
    int i = blockIdx.x * blockDim.x + threadIdx.x;
    if (i >= n4) return;
    float4 v = ((const float4*)in)[i];
    union { uint4 u; __half2 p[4]; } pk;
    pk.p[0] = split1(v.x); pk.p[1] = split1(v.y);
    pk.p[2] = split1(v.z); pk.p[3] = split1(v.w);
    ((uint4*)out)[i] = pk.u;
}

// W[1024,1024] -> Wt_split[n][2k] (transpose + split)
__global__ __launch_bounds__(256) void split_w_t(
    const float* __restrict__ W, __half* __restrict__ Wt)
{
    __shared__ float t[32][33];
    const int bn = blockIdx.x, bk = blockIdx.y;
    const int tx = threadIdx.x, ty = threadIdx.y;   // 32 x 8
#pragma unroll
    for (int i = 0; i < 32; i += 8)
        t[ty + i][tx] = W[(size_t)(bk * 32 + ty + i) * D_ + bn * 32 + tx];
    __syncthreads();
    __half2* Wt2 = (__half2*)Wt;
#pragma unroll
    for (int i = 0; i < 32; i += 8) {
        int n = bn * 32 + ty + i;
        int k = bk * 32 + tx;
        Wt2[(size_t)n * 1024 + k] = split1(t[tx][ty + i]);
    }
}

// ---------------------------------------------------------------------------
// HMMA GEMM (unchanged from R5, validated)
// ---------------------------------------------------------------------------
#define STAGE_BYTES 32768
#define SMEM_B_OFF  16384

__device__ __forceinline__ uint32_t smem_u32(const void* p) {
    uint32_t a;
    asm("{ .reg .u64 t; cvta.to.shared.u64 t, %1; cvt.u32.u64 %0, t; }"
        : "=r"(a) : "l"(p));
    return a;
}

__device__ __forceinline__ void cp16(uint32_t dst, const void* src) {
    asm volatile("cp.async.cg.shared.global [%0], [%1], 16;\n"
                 :: "r"(dst), "l"(src));
}

__global__ __launch_bounds__(256) void gemm_tc(
    const __half* __restrict__ A,
    const __half* __restrict__ Bt,
    float* __restrict__ C, int remap)
{
    extern __shared__ char smem[];
    const uint32_t sbase = smem_u32(smem);
    const int tid = threadIdx.x;
    const int wid = tid >> 5;
    const int lid = tid & 31;
    const int wm  = wid >> 2;
    const int wn  = wid & 3;
    const int nb = blockIdx.x;
    const int mb = blockIdx.y;

    const __half* Ab = A  + (size_t)(mb * 128) * K2_;
    const __half* Bb = Bt + (size_t)(nb * 128) * K2_;

    uint32_t soff[4]; int lr[4], lc[4];
#pragma unroll
    for (int i = 0; i < 4; i++) {
        int idx = i * 256 + tid;
        int r = idx >> 3, c = idx & 7;
        lr[i] = r; lc[i] = c;
        soff[i] = (uint32_t)(r * 128 + (c ^ (r & 7)) * 16);
    }

    float acc[4][4][4];
#pragma unroll
    for (int mi = 0; mi < 4; mi++)
#pragma unroll
        for (int ni = 0; ni < 4; ni++)
#pragma unroll
            for (int e = 0; e < 4; e++) acc[mi][ni][e] = 0.0f;

    const int a_row = wm * 64 + (lid & 15);
    const int a_kh  = lid >> 4;
    const int b_row = wn * 32 + ((lid >> 4) * 8) + (lid & 7);
    const int b_kh  = (lid >> 3) & 1;

#pragma unroll
    for (int i = 0; i < 4; i++) {
        cp16(sbase + soff[i],              Ab + (size_t)lr[i] * K2_ + lc[i] * 8);
        cp16(sbase + SMEM_B_OFF + soff[i], Bb + (size_t)lr[i] * K2_ + lc[i] * 8);
    }
    asm volatile("cp.async.commit_group;\n");

    for (int it = 0; it < NT_; ++it) {
        if (it + 1 < NT_) {
            const uint32_t st = sbase + ((it + 1) & 1) * STAGE_BYTES;
            const int k0 = (it + 1) * 64;
#pragma unroll
            for (int i = 0; i < 4; i++) {
                cp16(st + soff[i],              Ab + (size_t)lr[i] * K2_ + k0 + lc[i] * 8);
                cp16(st + SMEM_B_OFF + soff[i], Bb + (size_t)lr[i] * K2_ + k0 + lc[i] * 8);
            }
            asm volatile("cp.async.commit_group;\n");
            asm volatile("cp.async.wait_group 1;\n");
        } else {
            asm volatile("cp.async.wait_group 0;\n");
        }
        __syncthreads();

        const uint32_t sa = sbase + (it & 1) * STAGE_BYTES;
        const uint32_t sb = sa + SMEM_B_OFF;

#pragma unroll
        for (int k16 = 0; k16 < 4; k16++) {
            uint32_t af[4][4];
#pragma unroll
            for (int mi = 0; mi < 4; mi++) {
                int row = a_row + mi * 16;
                int ch  = (k16 * 2 + a_kh) ^ (row & 7);
                uint32_t ad = sa + row * 128 + ch * 16;
                asm volatile(
                    "ldmatrix.sync.aligned.m8n8.x4.shared.b16 {%0,%1,%2,%3}, [%4];"
                    : "=r"(af[mi][0]), "=r"(af[mi][1]), "=r"(af[mi][2]), "=r"(af[mi][3])
                    : "r"(ad));
            }
            uint32_t bf[4][2];
#pragma unroll
            for (int nj = 0; nj < 2; nj++) {
                int row = b_row + nj * 16;
                int ch  = (k16 * 2 + b_kh) ^ (row & 7);
                uint32_t bd = sb + row * 128 + ch * 16;
                uint32_t r0, r1, r2, r3;
                asm volatile(
                    "ldmatrix.sync.aligned.m8n8.x4.shared.b16 {%0,%1,%2,%3}, [%4];"
                    : "=r"(r0), "=r"(r1), "=r"(r2), "=r"(r3)
                    : "r"(bd));
                bf[nj * 2 + 0][0] = r0; bf[nj * 2 + 0][1] = r1;
                bf[nj * 2 + 1][0] = r2; bf[nj * 2 + 1][1] = r3;
            }
#pragma unroll
            for (int mi = 0; mi < 4; mi++)
#pragma unroll
                for (int ni = 0; ni < 4; ni++) {
                    asm volatile(
                        "mma.sync.aligned.m16n8k16.row.col.f32.f16.f16.f32 "
                        "{%0,%1,%2,%3}, {%4,%5,%6,%7}, {%8,%9}, {%0,%1,%2,%3};"
                        : "+f"(acc[mi][ni][0]), "+f"(acc[mi][ni][1]),
                          "+f"(acc[mi][ni][2]), "+f"(acc[mi][ni][3])
                        : "r"(af[mi][0]), "r"(af[mi][1]), "r"(af[mi][2]), "r"(af[mi][3]),
                          "r"(bf[ni][0]), "r"(bf[ni][1]));
                }
        }
        __syncthreads();
    }

    const int tq = lid >> 2;
    const int tr = lid & 3;
#pragma unroll
    for (int mi = 0; mi < 4; mi++) {
#pragma unroll
        for (int half_ = 0; half_ < 2; half_++) {
            int m = mb * 128 + wm * 64 + mi * 16 + tq + half_ * 8;
#pragma unroll
            for (int ni = 0; ni < 4; ni++) {
                int n = nb * 128 + wn * 32 + ni * 8 + tr * 2;
                float2 v;
                v.x = acc[mi][ni][half_ * 2 + 0];
                v.y = acc[mi][ni][half_ * 2 + 1];
                if (remap == 0) {
                    *(float2*)(C + (size_t)m * D_ + n) = v;
                } else {
                    int bb = m >> 6, ll = m & 63;
                    int h  = n >> 6, dh = n & 63;
                    *(float2*)(C + (((size_t)(bb * H_ + h) * L_ + ll) * DH_ + dh)) = v;
                }
            }
        }
    }
}

// ---------------------------------------------------------------------------
// Tensor-core attention: one block per (b,h), 4 warps x 16 Q-rows.
// S = Q.K^T via 3-term split (K'=192): A=(qhi,qlo,qhi), B=(khi,khi,klo).
// P.V via K'=128: A=(phi,plo) built from S frags via shfl, B=(vhi,vhi) dup rows.
// ---------------------------------------------------------------------------
#define QK_ROWB 400               // bytes per Q/K smem row (192 halfs + pad)
#define V_ROWB  144               // bytes per V smem row (64 halfs + pad)
#define AT_QS   0
#define AT_KS   (64 * QK_ROWB)    // 25600
#define AT_VS   (2 * 64 * QK_ROWB)// 51200
#define AT_SMEM (AT_VS + 128 * V_ROWB)  // 69632

__global__ __launch_bounds__(128, 3) void attn_tc(
    const float* __restrict__ gq, const float* __restrict__ gk,
    const float* __restrict__ gv, const float* __restrict__ gbias,
    __half* __restrict__ gout)
{
    extern __shared__ char smc[];
    const uint32_t sb = smem_u32(smc);
    const int tid = threadIdx.x;
    const int wid = tid >> 5;
    const int lid = tid & 31;
    const int bh  = blockIdx.x;
    const int b   = bh >> 4;
    const int h   = bh & 15;
    const size_t base = (size_t)bh * (L_ * DH_);

    // ---- load + convert Q,K,V into smem ----
#pragma unroll
    for (int it = 0; it < 8; it++) {
        int e   = it * 128 + tid;     // 0..1023 float4 slots
        int row = e >> 4;
        int c4  = e & 15;
        float4 q4 = *(const float4*)(gq + base + row * 64 + c4 * 4);
        float4 k4 = *(const float4*)(gk + base + row * 64 + c4 * 4);
        float4 v4 = *(const float4*)(gv + base + row * 64 + c4 * 4);
        const float qv[4] = {q4.x, q4.y, q4.z, q4.w};
        const float kv[4] = {k4.x, k4.y, k4.z, k4.w};
        union { uint2 u[3]; __half hh[12]; } uq, uk;
#pragma unroll
        for (int e4 = 0; e4 < 4; e4++) {
            __half2 qs = split1(qv[e4]);
            __half  kh = __float2half_rn(kv[e4]);
            __half  kl = __float2half_rn(kv[e4] - __half2float(kh));
            uq.hh[3 * e4 + 0] = qs.x; uq.hh[3 * e4 + 1] = qs.y; uq.hh[3 * e4 + 2] = qs.x;
            uk.hh[3 * e4 + 0] = kh;   uk.hh[3 * e4 + 1] = kh;   uk.hh[3 * e4 + 2] = kl;
        }
        char* qp = smc + AT_QS + row * QK_ROWB + c4 * 24;
        char* kp = smc + AT_KS + row * QK_ROWB + c4 * 24;
#pragma unroll
        for (int u = 0; u < 3; u++) {
            *(uint2*)(qp + u * 8) = uq.u[u];
            *(uint2*)(kp + u * 8) = uk.u[u];
        }
        union { uint2 u; __half hh[4]; } uv;
        uv.hh[0] = __float2half_rn(v4.x); uv.hh[1] = __float2half_rn(v4.y);
        uv.hh[2] = __float2half_rn(v4.z); uv.hh[3] = __float2half_rn(v4.w);
        *(uint2*)(smc + AT_VS + (2 * row + 0) * V_ROWB + c4 * 8) = uv.u;
        *(uint2*)(smc + AT_VS + (2 * row + 1) * V_ROWB + c4 * 8) = uv.u;
    }
    __syncthreads();

    // ---- S = Q.K^T (K'=192: 12 k16 tiles, 8 n-tiles) ----
    float SA[8][4];
#pragma unroll
    for (int j = 0; j < 8; j++)
#pragma unroll
        for (int e = 0; e < 4; e++) SA[j][e] = 0.0f;

    const uint32_t a_addr0 = sb + AT_QS + (wid * 16 + (lid & 15)) * QK_ROWB + (lid >> 4) * 16;
    const uint32_t b_rowsel = ((lid >> 4) * 8) + (lid & 7);
    const uint32_t b_khalf  = ((lid >> 3) & 1) * 16;

#pragma unroll
    for (int t = 0; t < 12; t++) {
        uint32_t a0, a1, a2, a3;
        asm volatile(
            "ldmatrix.sync.aligned.m8n8.x4.shared.b16 {%0,%1,%2,%3}, [%4];"
            : "=r"(a0), "=r"(a1), "=r"(a2), "=r"(a3)
            : "r"(a_addr0 + t * 32));
#pragma unroll
        for (int np = 0; np < 4; np++) {
            uint32_t b0, b1, b2, b3;
            uint32_t bd = sb + AT_KS + (np * 16 + b_rowsel) * QK_ROWB + t * 32 + b_khalf;
            asm volatile(
                "ldmatrix.sync.aligned.m8n8.x4.shared.b16 {%0,%1,%2,%3}, [%4];"
                : "=r"(b0), "=r"(b1), "=r"(b2), "=r"(b3)
                : "r"(bd));
            asm volatile(
                "mma.sync.aligned.m16n8k16.row.col.f32.f16.f16.f32 "
                "{%0,%1,%2,%3}, {%4,%5,%6,%7}, {%8,%9}, {%0,%1,%2,%3};"
                : "+f"(SA[2 * np][0]), "+f"(SA[2 * np][1]),
                  "+f"(SA[2 * np][2]), "+f"(SA[2 * np][3])
                : "r"(a0), "r"(a1), "r"(a2), "r"(a3), "r"(b0), "r"(b1));
            asm volatile(
                "mma.sync.aligned.m16n8k16.row.col.f32.f16.f16.f32 "
                "{%0,%1,%2,%3}, {%4,%5,%6,%7}, {%8,%9}, {%0,%1,%2,%3};"
                : "+f"(SA[2 * np + 1][0]), "+f"(SA[2 * np + 1][1]),
                  "+f"(SA[2 * np + 1][2]), "+f"(SA[2 * np + 1][3])
                : "r"(a0), "r"(a1), "r"(a2), "r"(a3), "r"(b2), "r"(b3));
        }
    }

    // ---- softmax (rows r and r+8) ----
    const int r = lid >> 2;
    const int c = lid & 3;
    const int qr = wid * 16 + r;
    const float* bp0 = gbias + (size_t)h * 4096 + qr * 64;
    const float* bp8 = bp0 + 8 * 64;

    float mx0 = -1e30f, mx8 = -1e30f;
#pragma unroll
    for (int j = 0; j < 8; j++) {
        float2 bb0 = *(const float2*)(bp0 + 8 * j + 2 * c);
        float2 bb8 = *(const float2*)(bp8 + 8 * j + 2 * c);
        SA[j][0] = SA[j][0] * 0.125f + bb0.x;
        SA[j][1] = SA[j][1] * 0.125f + bb0.y;
        SA[j][2] = SA[j][2] * 0.125f + bb8.x;
        SA[j][3] = SA[j][3] * 0.125f + bb8.y;
        mx0 = fmaxf(mx0, fmaxf(SA[j][0], SA[j][1]));
        mx8 = fmaxf(mx8, fmaxf(SA[j][2], SA[j][3]));
    }
    mx0 = fmaxf(mx0, __shfl_xor_sync(0xffffffffu, mx0, 1));
    mx0 = fmaxf(mx0, __shfl_xor_sync(0xffffffffu, mx0, 2));
    mx8 = fmaxf(mx8, __shfl_xor_sync(0xffffffffu, mx8, 1));
    mx8 = fmaxf(mx8, __shfl_xor_sync(0xffffffffu, mx8, 2));

    float s0 = 0.0f, s8 = 0.0f;
#pragma unroll
    for (int j = 0; j < 8; j++) {
        SA[j][0] = __expf(SA[j][0] - mx0); s0 += SA[j][0];
        SA[j][1] = __expf(SA[j][1] - mx0); s0 += SA[j][1];
        SA[j][2] = __expf(SA[j][2] - mx8); s8 += SA[j][2];
        SA[j][3] = __expf(SA[j][3] - mx8); s8 += SA[j][3];
    }
    s0 += __shfl_xor_sync(0xffffffffu, s0, 1);
    s0 += __shfl_xor_sync(0xffffffffu, s0, 2);
    s8 += __shfl_xor_sync(0xffffffffu, s8, 1);
    s8 += __shfl_xor_sync(0xffffffffu, s8, 2);
    const float inv0 = 1.0f / s0, inv8 = 1.0f / s8;
#pragma unroll
    for (int j = 0; j < 8; j++) {
        SA[j][0] *= inv0; SA[j][1] *= inv0;
        SA[j][2] *= inv8; SA[j][3] *= inv8;
    }

    // ---- O = P.V (K'=128: 8 k16 tiles over dup'd V rows) ----
    float OA[8][4];
#pragma unroll
    for (int j = 0; j < 8; j++)
#pragma unroll
        for (int e = 0; e < 4; e++) OA[j][e] = 0.0f;

    const int l1 = (lid & ~3) | (c >> 1);
    const int l2 = l1 + 2;
    const int selb = c & 1;
    const uint32_t v_row = (lid & 7) + 8 * ((lid >> 3) & 1);
    const uint32_t v_col = ((lid >> 4) * 8) * 2;

#pragma unroll
    for (int t = 0; t < 8; t++) {
        float s00 = __shfl_sync(0xffffffffu, SA[t][0], l1);
        float s01 = __shfl_sync(0xffffffffu, SA[t][1], l1);
        float s02 = __shfl_sync(0xffffffffu, SA[t][2], l1);
        float s03 = __shfl_sync(0xffffffffu, SA[t][3], l1);
        float s10 = __shfl_sync(0xffffffffu, SA[t][0], l2);
        float s11 = __shfl_sync(0xffffffffu, SA[t][1], l2);
        float s12 = __shfl_sync(0xffffffffu, SA[t][2], l2);
        float s13 = __shfl_sync(0xffffffffu, SA[t][3], l2);
        float v0 = selb ? s01 : s00;   // p[r][8t+c]
        float v1 = selb ? s03 : s02;   // p[r+8][8t+c]
        float v2 = selb ? s11 : s10;   // p[r][8t+4+c]
        float v3 = selb ? s13 : s12;   // p[r+8][8t+4+c]
        union { uint32_t u; __half2 p; } a0, a1, a2, a3;
        a0.p = split1(v0); a1.p = split1(v1);
        a2.p = split1(v2); a3.p = split1(v3);

#pragma unroll
        for (int dp = 0; dp < 4; dp++) {
            uint32_t bd = sb + AT_VS + (16 * t + v_row) * V_ROWB + dp * 32 + v_col;
            uint32_t b0, b1, b2, b3;
            asm volatile(
                "ldmatrix.sync.aligned.m8n8.x4.trans.shared.b16 {%0,%1,%2,%3}, [%4];"
                : "=r"(b0), "=r"(b1), "=r"(b2), "=r"(b3)
                : "r"(bd));
            asm volatile(
                "mma.sync.aligned.m16n8k16.row.col.f32.f16.f16.f32 "
                "{%0,%1,%2,%3}, {%4,%5,%6,%7}, {%8,%9}, {%0,%1,%2,%3};"
                : "+f"(OA[2 * dp][0]), "+f"(OA[2 * dp][1]),
                  "+f"(OA[2 * dp][2]), "+f"(OA[2 * dp][3])
                : "r"(a0.u), "r"(a1.u), "r"(a2.u), "r"(a3.u), "r"(b0), "r"(b1));
            asm volatile(
                "mma.sync.aligned.m16n8k16.row.col.f32.f16.f16.f32 "
                "{%0,%1,%2,%3}, {%4,%5,%6,%7}, {%8,%9}, {%0,%1,%2,%3};"
                : "+f"(OA[2 * dp + 1][0]), "+f"(OA[2 * dp + 1][1]),
                  "+f"(OA[2 * dp + 1][2]), "+f"(OA[2 * dp + 1][3])
                : "r"(a0.u), "r"(a1.u), "r"(a2.u), "r"(a3.u), "r"(b2), "r"(b3));
        }
    }

    // ---- epilogue: split-write to g_ats [M, 2048] ----
    const int m = b * 64 + qr;
#pragma unroll
    for (int j = 0; j < 8; j++) {
        int d = 8 * j + 2 * c;
        size_t col = (size_t)(h * 64 + d);
        union { uint2 u; __half2 p[2]; } w;
        w.p[0] = split1(OA[j][0]); w.p[1] = split1(OA[j][1]);
        *(uint2*)(gout + 2 * ((size_t)m * 1024 + col)) = w.u;
        w.p[0] = split1(OA[j][2]); w.p[1] = split1(OA[j][3]);
        *(uint2*)(gout + 2 * ((size_t)(m + 8) * 1024 + col)) = w.u;
    }
}

// ---------------------------------------------------------------------------
// Launch
// ---------------------------------------------------------------------------
extern "C" void kernel_launch(void* const* d_in, const int* in_sizes, int n_in,
                              void* d_out, int out_size)
{
    const float* x    = (const float*)d_in[0];
    const float* bias = (const float*)d_in[1];
    const float* Wq   = (const float*)d_in[2];
    const float* Wk   = (const float*)d_in[3];
    const float* Wv   = (const float*)d_in[4];
    const float* Wo   = (const float*)d_in[5];
    float* out = (float*)d_out;

    void *pxs, *pats, *pwq, *pwk, *pwv, *pwo, *pq, *pk, *pv;
    cudaGetSymbolAddress(&pxs,  g_xs);
    cudaGetSymbolAddress(&pats, g_ats);
    cudaGetSymbolAddress(&pwq,  g_wq);
    cudaGetSymbolAddress(&pwk,  g_wk);
    cudaGetSymbolAddress(&pwv,  g_wv);
    cudaGetSymbolAddress(&pwo,  g_wo);
    cudaGetSymbolAddress(&pq,   g_q);
    cudaGetSymbolAddress(&pk,   g_k);
    cudaGetSymbolAddress(&pv,   g_v);

    // 1. split inputs
    split_rows<<<(M_ * D_ / 4 + 255) / 256, 256>>>(x, (__half*)pxs, M_ * D_ / 4);
    dim3 wt_threads(32, 8), wt_grid(32, 32);
    split_w_t<<<wt_grid, wt_threads>>>(Wq, (__half*)pwq);
    split_w_t<<<wt_grid, wt_threads>>>(Wk, (__half*)pwk);
    split_w_t<<<wt_grid, wt_threads>>>(Wv, (__half*)pwv);
    split_w_t<<<wt_grid, wt_threads>>>(Wo, (__half*)pwo);

    // 2. QKV projections on HMMA
    const int smem_gemm = 2 * STAGE_BYTES;   // 64 KB
    cudaFuncSetAttribute(gemm_tc, cudaFuncAttributeMaxDynamicSharedMemorySize, smem_gemm);
    dim3 gg(D_ / 128, M_ / 128);   // (8, 256)
    gemm_tc<<<gg, 256, smem_gemm>>>((const __half*)pxs, (const __half*)pwq, (float*)pq, 1);
    gemm_tc<<<gg, 256, smem_gemm>>>((const __half*)pxs, (const __half*)pwk, (float*)pk, 1);
    gemm_tc<<<gg, 256, smem_gemm>>>((const __half*)pxs, (const __half*)pwv, (float*)pv, 1);

    // 3. tensor-core attention (emits fp16 split)
    cudaFuncSetAttribute(attn_tc, cudaFuncAttributeMaxDynamicSharedMemorySize, AT_SMEM);
    attn_tc<<<B_ * H_, 128, AT_SMEM>>>((const float*)pq, (const float*)pk,
                                       (const float*)pv, bias, (__half*)pats);

    // 4. output projection
    gemm_tc<<<gg, 256, smem_gemm>>>((const __half*)pats, (const __half*)pwo, out, 0);
}

// round 9
// speedup vs baseline: 4.4782x; 1.0288x over previous
#include <cuda_runtime.h>
#include <cuda_fp16.h>
#include <cstdint>
#include <math.h>

// Problem constants
#define B_   512
#define L_   64
#define H_   16
#define DH_  64
#define D_   1024
#define M_   (B_ * L_)        // 32768
#define K2_  2048             // split K (hi/lo interleaved)
#define NT_  (K2_ / 64)       // 32 K-tiles of 64 halfs

// ---------------------------------------------------------------------------
// Scratch (__device__ globals — no allocations allowed)
// ---------------------------------------------------------------------------
__device__ __half g_xs  [(size_t)M_ * K2_];        // x split     [M, 2K]
__device__ __half g_ats [(size_t)M_ * K2_];        // attn split  [M, 2K]
__device__ __half g_wqkv[(size_t)3 * D_ * K2_];    // [Wq;Wk;Wv]^T split
__device__ __half g_wo  [(size_t)D_ * K2_];
__device__ float g_q[(size_t)B_ * H_ * L_ * DH_];  // [B,H,L,Dh] fp32
__device__ float g_k[(size_t)B_ * H_ * L_ * DH_];
__device__ float g_v[(size_t)B_ * H_ * L_ * DH_];

// ---------------------------------------------------------------------------
// fp32 -> (hi,lo) fp16 split
// ---------------------------------------------------------------------------
__device__ __forceinline__ __half2 split1(float v) {
    __half hi = __float2half_rn(v);
    __half lo = __float2half_rn(v - __half2float(hi));
    __half2 p; p.x = hi; p.y = lo; return p;
}

__global__ __launch_bounds__(256) void split_rows(
    const float* __restrict__ in, __half* __restrict__ out, int n4)
{
    int i = blockIdx.x * blockDim.x + threadIdx.x;
    if (i >= n4) return;
    float4 v = ((const float4*)in)[i];
    union { uint4 u; __half2 p[4]; } pk;
    pk.p[0] = split1(v.x); pk.p[1] = split1(v.y);
    pk.p[2] = split1(v.z); pk.p[3] = split1(v.w);
    ((uint4*)out)[i] = pk.u;
}

// W[1024,1024] -> Wt_split[n][2k] (transpose + split)
__global__ __launch_bounds__(256) void split_w_t(
    const float* __restrict__ W, __half* __restrict__ Wt)
{
    __shared__ float t[32][33];
    const int bn = blockIdx.x, bk = blockIdx.y;
    const int tx = threadIdx.x, ty = threadIdx.y;   // 32 x 8
#pragma unroll
    for (int i = 0; i < 32; i += 8)
        t[ty + i][tx] = W[(size_t)(bk * 32 + ty + i) * D_ + bn * 32 + tx];
    __syncthreads();
    __half2* Wt2 = (__half2*)Wt;
#pragma unroll
    for (int i = 0; i < 32; i += 8) {
        int n = bn * 32 + ty + i;
        int k = bk * 32 + tx;
        Wt2[(size_t)n * 1024 + k] = split1(t[tx][ty + i]);
    }
}

// ---------------------------------------------------------------------------
// HMMA GEMM, 3-stage cp.async pipeline.
// mode 0: C0[M,1024] row-major (Wo projection)
// mode 1: fused QKV — nb in [0,24): which = nb>>3 selects C0/C1/C2, scatter
//         to [B,H,L,Dh].
// 128x128 tile, BK=64, 8 warps (2m x 4n), warp tile 64x32, mma.m16n8k16.
// ---------------------------------------------------------------------------
#define STAGE_BYTES 32768          // A(16K) + B(16K) per stage
#define SMEM_B_OFF  16384
#define N_STAGE     3

__device__ __forceinline__ uint32_t smem_u32(const void* p) {
    uint32_t a;
    asm("{ .reg .u64 t; cvta.to.shared.u64 t, %1; cvt.u32.u64 %0, t; }"
        : "=r"(a) : "l"(p));
    return a;
}

__device__ __forceinline__ void cp16(uint32_t dst, const void* src) {
    asm volatile("cp.async.cg.shared.global [%0], [%1], 16;\n"
                 :: "r"(dst), "l"(src));
}

__global__ __launch_bounds__(256) void gemm_ms(
    const __half* __restrict__ A,
    const __half* __restrict__ Bt,
    float* __restrict__ C0, float* __restrict__ C1, float* __restrict__ C2,
    int mode)
{
    extern __shared__ char smem[];
    const uint32_t sbase = smem_u32(smem);
    const int tid = threadIdx.x;
    const int wid = tid >> 5;
    const int lid = tid & 31;
    const int wm  = wid >> 2;          // 0..1  (64 rows)
    const int wn  = wid & 3;           // 0..3  (32 cols)
    const int nb = blockIdx.x;
    const int mb = blockIdx.y;

    const __half* Ab = A  + (size_t)(mb * 128) * K2_;
    const __half* Bb = Bt + (size_t)(nb * 128) * K2_;

    // per-thread load pattern: 4 x 16B chunks per operand per stage
    uint32_t soff[4]; int lr[4], lc[4];
#pragma unroll
    for (int i = 0; i < 4; i++) {
        int idx = i * 256 + tid;
        int r = idx >> 3, c = idx & 7;
        lr[i] = r; lc[i] = c;
        soff[i] = (uint32_t)(r * 128 + (c ^ (r & 7)) * 16);
    }

    float acc[4][4][4];
#pragma unroll
    for (int mi = 0; mi < 4; mi++)
#pragma unroll
        for (int ni = 0; ni < 4; ni++)
#pragma unroll
            for (int e = 0; e < 4; e++) acc[mi][ni][e] = 0.0f;

    const int a_row = wm * 64 + (lid & 15);
    const int a_kh  = lid >> 4;
    const int b_row = wn * 32 + ((lid >> 4) * 8) + (lid & 7);
    const int b_kh  = (lid >> 3) & 1;

    // prologue: stages 0,1
#pragma unroll
    for (int s = 0; s < 2; s++) {
        const uint32_t st = sbase + s * STAGE_BYTES;
        const int k0 = s * 64;
#pragma unroll
        for (int i = 0; i < 4; i++) {
            cp16(st + soff[i],              Ab + (size_t)lr[i] * K2_ + k0 + lc[i] * 8);
            cp16(st + SMEM_B_OFF + soff[i], Bb + (size_t)lr[i] * K2_ + k0 + lc[i] * 8);
        }
        asm volatile("cp.async.commit_group;\n");
    }

    int cm_stage = 0;   // stage being computed
    int ld_stage = 2;   // stage to load next

    for (int it = 0; it < NT_; ++it) {
        if (it + 1 < NT_) asm volatile("cp.async.wait_group 1;\n");
        else              asm volatile("cp.async.wait_group 0;\n");
        __syncthreads();

        // issue loads for stage it+2 (slot freed by compute of it-1)
        if (it + 2 < NT_) {
            const uint32_t st = sbase + ld_stage * STAGE_BYTES;
            const int k0 = (it + 2) * 64;
#pragma unroll
            for (int i = 0; i < 4; i++) {
                cp16(st + soff[i],              Ab + (size_t)lr[i] * K2_ + k0 + lc[i] * 8);
                cp16(st + SMEM_B_OFF + soff[i], Bb + (size_t)lr[i] * K2_ + k0 + lc[i] * 8);
            }
            asm volatile("cp.async.commit_group;\n");
            if (++ld_stage == N_STAGE) ld_stage = 0;
        }

        const uint32_t sa = sbase + cm_stage * STAGE_BYTES;
        const uint32_t sb = sa + SMEM_B_OFF;
        if (++cm_stage == N_STAGE) cm_stage = 0;

#pragma unroll
        for (int k16 = 0; k16 < 4; k16++) {
            uint32_t af[4][4];
#pragma unroll
            for (int mi = 0; mi < 4; mi++) {
                int row = a_row + mi * 16;
                int ch  = (k16 * 2 + a_kh) ^ (row & 7);
                uint32_t ad = sa + row * 128 + ch * 16;
                asm volatile(
                    "ldmatrix.sync.aligned.m8n8.x4.shared.b16 {%0,%1,%2,%3}, [%4];"
                    : "=r"(af[mi][0]), "=r"(af[mi][1]), "=r"(af[mi][2]), "=r"(af[mi][3])
                    : "r"(ad));
            }
            uint32_t bf[4][2];
#pragma unroll
            for (int nj = 0; nj < 2; nj++) {
                int row = b_row + nj * 16;
                int ch  = (k16 * 2 + b_kh) ^ (row & 7);
                uint32_t bd = sb + row * 128 + ch * 16;
                uint32_t r0, r1, r2, r3;
                asm volatile(
                    "ldmatrix.sync.aligned.m8n8.x4.shared.b16 {%0,%1,%2,%3}, [%4];"
                    : "=r"(r0), "=r"(r1), "=r"(r2), "=r"(r3)
                    : "r"(bd));
                bf[nj * 2 + 0][0] = r0; bf[nj * 2 + 0][1] = r1;
                bf[nj * 2 + 1][0] = r2; bf[nj * 2 + 1][1] = r3;
            }
#pragma unroll
            for (int mi = 0; mi < 4; mi++)
#pragma unroll
                for (int ni = 0; ni < 4; ni++) {
                    asm volatile(
                        "mma.sync.aligned.m16n8k16.row.col.f32.f16.f16.f32 "
                        "{%0,%1,%2,%3}, {%4,%5,%6,%7}, {%8,%9}, {%0,%1,%2,%3};"
                        : "+f"(acc[mi][ni][0]), "+f"(acc[mi][ni][1]),
                          "+f"(acc[mi][ni][2]), "+f"(acc[mi][ni][3])
                        : "r"(af[mi][0]), "r"(af[mi][1]), "r"(af[mi][2]), "r"(af[mi][3]),
                          "r"(bf[ni][0]), "r"(bf[ni][1]));
                }
        }
    }

    // Epilogue
    float* Cs;
    int nbase;
    if (mode == 0) {
        Cs = C0;
        nbase = nb * 128;
    } else {
        const int which = nb >> 3;
        Cs = (which == 0) ? C0 : (which == 1) ? C1 : C2;
        nbase = (nb & 7) * 128;
    }

    const int tq = lid >> 2;
    const int tr = lid & 3;
#pragma unroll
    for (int mi = 0; mi < 4; mi++) {
#pragma unroll
        for (int half_ = 0; half_ < 2; half_++) {
            int m = mb * 128 + wm * 64 + mi * 16 + tq + half_ * 8;
#pragma unroll
            for (int ni = 0; ni < 4; ni++) {
                int n = nbase + wn * 32 + ni * 8 + tr * 2;
                float2 v;
                v.x = acc[mi][ni][half_ * 2 + 0];
                v.y = acc[mi][ni][half_ * 2 + 1];
                if (mode == 0) {
                    *(float2*)(Cs + (size_t)m * D_ + n) = v;
                } else {
                    int bb = m >> 6, ll = m & 63;
                    int h  = n >> 6, dh = n & 63;
                    *(float2*)(Cs + (((size_t)(bb * H_ + h) * L_ + ll) * DH_ + dh)) = v;
                }
            }
        }
    }
}

// ---------------------------------------------------------------------------
// Tensor-core attention (validated in R7): one block per (b,h), 4 warps.
// ---------------------------------------------------------------------------
#define QK_ROWB 400
#define V_ROWB  144
#define AT_QS   0
#define AT_KS   (64 * QK_ROWB)
#define AT_VS   (2 * 64 * QK_ROWB)
#define AT_SMEM (AT_VS + 128 * V_ROWB)  // 69632

__global__ __launch_bounds__(128, 3) void attn_tc(
    const float* __restrict__ gq, const float* __restrict__ gk,
    const float* __restrict__ gv, const float* __restrict__ gbias,
    __half* __restrict__ gout)
{
    extern __shared__ char smc[];
    const uint32_t sb = smem_u32(smc);
    const int tid = threadIdx.x;
    const int wid = tid >> 5;
    const int lid = tid & 31;
    const int bh  = blockIdx.x;
    const int b   = bh >> 4;
    const int h   = bh & 15;
    const size_t base = (size_t)bh * (L_ * DH_);

#pragma unroll
    for (int it = 0; it < 8; it++) {
        int e   = it * 128 + tid;
        int row = e >> 4;
        int c4  = e & 15;
        float4 q4 = *(const float4*)(gq + base + row * 64 + c4 * 4);
        float4 k4 = *(const float4*)(gk + base + row * 64 + c4 * 4);
        float4 v4 = *(const float4*)(gv + base + row * 64 + c4 * 4);
        const float qv[4] = {q4.x, q4.y, q4.z, q4.w};
        const float kv[4] = {k4.x, k4.y, k4.z, k4.w};
        union { uint2 u[3]; __half hh[12]; } uq, uk;
#pragma unroll
        for (int e4 = 0; e4 < 4; e4++) {
            __half2 qs = split1(qv[e4]);
            __half  kh = __float2half_rn(kv[e4]);
            __half  kl = __float2half_rn(kv[e4] - __half2float(kh));
            uq.hh[3 * e4 + 0] = qs.x; uq.hh[3 * e4 + 1] = qs.y; uq.hh[3 * e4 + 2] = qs.x;
            uk.hh[3 * e4 + 0] = kh;   uk.hh[3 * e4 + 1] = kh;   uk.hh[3 * e4 + 2] = kl;
        }
        char* qp = smc + AT_QS + row * QK_ROWB + c4 * 24;
        char* kp = smc + AT_KS + row * QK_ROWB + c4 * 24;
#pragma unroll
        for (int u = 0; u < 3; u++) {
            *(uint2*)(qp + u * 8) = uq.u[u];
            *(uint2*)(kp + u * 8) = uk.u[u];
        }
        union { uint2 u; __half hh[4]; } uv;
        uv.hh[0] = __float2half_rn(v4.x); uv.hh[1] = __float2half_rn(v4.y);
        uv.hh[2] = __float2half_rn(v4.z); uv.hh[3] = __float2half_rn(v4.w);
        *(uint2*)(smc + AT_VS + (2 * row + 0) * V_ROWB + c4 * 8) = uv.u;
        *(uint2*)(smc + AT_VS + (2 * row + 1) * V_ROWB + c4 * 8) = uv.u;
    }
    __syncthreads();

    float SA[8][4];
#pragma unroll
    for (int j = 0; j < 8; j++)
#pragma unroll
        for (int e = 0; e < 4; e++) SA[j][e] = 0.0f;

    const uint32_t a_addr0 = sb + AT_QS + (wid * 16 + (lid & 15)) * QK_ROWB + (lid >> 4) * 16;
    const uint32_t b_rowsel = ((lid >> 4) * 8) + (lid & 7);
    const uint32_t b_khalf  = ((lid >> 3) & 1) * 16;

#pragma unroll
    for (int t = 0; t < 12; t++) {
        uint32_t a0, a1, a2, a3;
        asm volatile(
            "ldmatrix.sync.aligned.m8n8.x4.shared.b16 {%0,%1,%2,%3}, [%4];"
            : "=r"(a0), "=r"(a1), "=r"(a2), "=r"(a3)
            : "r"(a_addr0 + t * 32));
#pragma unroll
        for (int np = 0; np < 4; np++) {
            uint32_t b0, b1, b2, b3;
            uint32_t bd = sb + AT_KS + (np * 16 + b_rowsel) * QK_ROWB + t * 32 + b_khalf;
            asm volatile(
                "ldmatrix.sync.aligned.m8n8.x4.shared.b16 {%0,%1,%2,%3}, [%4];"
                : "=r"(b0), "=r"(b1), "=r"(b2), "=r"(b3)
                : "r"(bd));
            asm volatile(
                "mma.sync.aligned.m16n8k16.row.col.f32.f16.f16.f32 "
                "{%0,%1,%2,%3}, {%4,%5,%6,%7}, {%8,%9}, {%0,%1,%2,%3};"
                : "+f"(SA[2 * np][0]), "+f"(SA[2 * np][1]),
                  "+f"(SA[2 * np][2]), "+f"(SA[2 * np][3])
                : "r"(a0), "r"(a1), "r"(a2), "r"(a3), "r"(b0), "r"(b1));
            asm volatile(
                "mma.sync.aligned.m16n8k16.row.col.f32.f16.f16.f32 "
                "{%0,%1,%2,%3}, {%4,%5,%6,%7}, {%8,%9}, {%0,%1,%2,%3};"
                : "+f"(SA[2 * np + 1][0]), "+f"(SA[2 * np + 1][1]),
                  "+f"(SA[2 * np + 1][2]), "+f"(SA[2 * np + 1][3])
                : "r"(a0), "r"(a1), "r"(a2), "r"(a3), "r"(b2), "r"(b3));
        }
    }

    const int r = lid >> 2;
    const int c = lid & 3;
    const int qr = wid * 16 + r;
    const float* bp0 = gbias + (size_t)h * 4096 + qr * 64;
    const float* bp8 = bp0 + 8 * 64;

    float mx0 = -1e30f, mx8 = -1e30f;
#pragma unroll
    for (int j = 0; j < 8; j++) {
        float2 bb0 = *(const float2*)(bp0 + 8 * j + 2 * c);
        float2 bb8 = *(const float2*)(bp8 + 8 * j + 2 * c);
        SA[j][0] = SA[j][0] * 0.125f + bb0.x;
        SA[j][1] = SA[j][1] * 0.125f + bb0.y;
        SA[j][2] = SA[j][2] * 0.125f + bb8.x;
        SA[j][3] = SA[j][3] * 0.125f + bb8.y;
        mx0 = fmaxf(mx0, fmaxf(SA[j][0], SA[j][1]));
        mx8 = fmaxf(mx8, fmaxf(SA[j][2], SA[j][3]));
    }
    mx0 = fmaxf(mx0, __shfl_xor_sync(0xffffffffu, mx0, 1));
    mx0 = fmaxf(mx0, __shfl_xor_sync(0xffffffffu, mx0, 2));
    mx8 = fmaxf(mx8, __shfl_xor_sync(0xffffffffu, mx8, 1));
    mx8 = fmaxf(mx8, __shfl_xor_sync(0xffffffffu, mx8, 2));

    float s0 = 0.0f, s8 = 0.0f;
#pragma unroll
    for (int j = 0; j < 8; j++) {
        SA[j][0] = __expf(SA[j][0] - mx0); s0 += SA[j][0];
        SA[j][1] = __expf(SA[j][1] - mx0); s0 += SA[j][1];
        SA[j][2] = __expf(SA[j][2] - mx8); s8 += SA[j][2];
        SA[j][3] = __expf(SA[j][3] - mx8); s8 += SA[j][3];
    }
    s0 += __shfl_xor_sync(0xffffffffu, s0, 1);
    s0 += __shfl_xor_sync(0xffffffffu, s0, 2);
    s8 += __shfl_xor_sync(0xffffffffu, s8, 1);
    s8 += __shfl_xor_sync(0xffffffffu, s8, 2);
    const float inv0 = 1.0f / s0, inv8 = 1.0f / s8;
#pragma unroll
    for (int j = 0; j < 8; j++) {
        SA[j][0] *= inv0; SA[j][1] *= inv0;
        SA[j][2] *= inv8; SA[j][3] *= inv8;
    }

    float OA[8][4];
#pragma unroll
    for (int j = 0; j < 8; j++)
#pragma unroll
        for (int e = 0; e < 4; e++) OA[j][e] = 0.0f;

    const int l1 = (lid & ~3) | (c >> 1);
    const int l2 = l1 + 2;
    const int selb = c & 1;
    const uint32_t v_row = (lid & 7) + 8 * ((lid >> 3) & 1);
    const uint32_t v_col = ((lid >> 4) * 8) * 2;

#pragma unroll
    for (int t = 0; t < 8; t++) {
        float s00 = __shfl_sync(0xffffffffu, SA[t][0], l1);
        float s01 = __shfl_sync(0xffffffffu, SA[t][1], l1);
        float s02 = __shfl_sync(0xffffffffu, SA[t][2], l1);
        float s03 = __shfl_sync(0xffffffffu, SA[t][3], l1);
        float s10 = __shfl_sync(0xffffffffu, SA[t][0], l2);
        float s11 = __shfl_sync(0xffffffffu, SA[t][1], l2);
        float s12 = __shfl_sync(0xffffffffu, SA[t][2], l2);
        float s13 = __shfl_sync(0xffffffffu, SA[t][3], l2);
        float v0 = selb ? s01 : s00;
        float v1 = selb ? s03 : s02;
        float v2 = selb ? s11 : s10;
        float v3 = selb ? s13 : s12;
        union { uint32_t u; __half2 p; } a0, a1, a2, a3;
        a0.p = split1(v0); a1.p = split1(v1);
        a2.p = split1(v2); a3.p = split1(v3);

#pragma unroll
        for (int dp = 0; dp < 4; dp++) {
            uint32_t bd = sb + AT_VS + (16 * t + v_row) * V_ROWB + dp * 32 + v_col;
            uint32_t b0, b1, b2, b3;
            asm volatile(
                "ldmatrix.sync.aligned.m8n8.x4.trans.shared.b16 {%0,%1,%2,%3}, [%4];"
                : "=r"(b0), "=r"(b1), "=r"(b2), "=r"(b3)
                : "r"(bd));
            asm volatile(
                "mma.sync.aligned.m16n8k16.row.col.f32.f16.f16.f32 "
                "{%0,%1,%2,%3}, {%4,%5,%6,%7}, {%8,%9}, {%0,%1,%2,%3};"
                : "+f"(OA[2 * dp][0]), "+f"(OA[2 * dp][1]),
                  "+f"(OA[2 * dp][2]), "+f"(OA[2 * dp][3])
                : "r"(a0.u), "r"(a1.u), "r"(a2.u), "r"(a3.u), "r"(b0), "r"(b1));
            asm volatile(
                "mma.sync.aligned.m16n8k16.row.col.f32.f16.f16.f32 "
                "{%0,%1,%2,%3}, {%4,%5,%6,%7}, {%8,%9}, {%0,%1,%2,%3};"
                : "+f"(OA[2 * dp + 1][0]), "+f"(OA[2 * dp + 1][1]),
                  "+f"(OA[2 * dp + 1][2]), "+f"(OA[2 * dp + 1][3])
                : "r"(a0.u), "r"(a1.u), "r"(a2.u), "r"(a3.u), "r"(b2), "r"(b3));
        }
    }

    const int m = b * 64 + qr;
#pragma unroll
    for (int j = 0; j < 8; j++) {
        int d = 8 * j + 2 * c;
        size_t col = (size_t)(h * 64 + d);
        union { uint2 u; __half2 p[2]; } w;
        w.p[0] = split1(OA[j][0]); w.p[1] = split1(OA[j][1]);
        *(uint2*)(gout + 2 * ((size_t)m * 1024 + col)) = w.u;
        w.p[0] = split1(OA[j][2]); w.p[1] = split1(OA[j][3]);
        *(uint2*)(gout + 2 * ((size_t)(m + 8) * 1024 + col)) = w.u;
    }
}

// ---------------------------------------------------------------------------
// Launch
// ---------------------------------------------------------------------------
extern "C" void kernel_launch(void* const* d_in, const int* in_sizes, int n_in,
                              void* d_out, int out_size)
{
    const float* x    = (const float*)d_in[0];
    const float* bias = (const float*)d_in[1];
    const float* Wq   = (const float*)d_in[2];
    const float* Wk   = (const float*)d_in[3];
    const float* Wv   = (const float*)d_in[4];
    const float* Wo   = (const float*)d_in[5];
    float* out = (float*)d_out;

    void *pxs, *pats, *pwqkv, *pwo, *pq, *pk, *pv;
    cudaGetSymbolAddress(&pxs,   g_xs);
    cudaGetSymbolAddress(&pats,  g_ats);
    cudaGetSymbolAddress(&pwqkv, g_wqkv);
    cudaGetSymbolAddress(&pwo,   g_wo);
    cudaGetSymbolAddress(&pq,    g_q);
    cudaGetSymbolAddress(&pk,    g_k);
    cudaGetSymbolAddress(&pv,    g_v);

    __half* wqkv = (__half*)pwqkv;

    // 1. split inputs
    split_rows<<<(M_ * D_ / 4 + 255) / 256, 256>>>(x, (__half*)pxs, M_ * D_ / 4);
    dim3 wt_threads(32, 8), wt_grid(32, 32);
    split_w_t<<<wt_grid, wt_threads>>>(Wq, wqkv);
    split_w_t<<<wt_grid, wt_threads>>>(Wk, wqkv + (size_t)D_ * K2_);
    split_w_t<<<wt_grid, wt_threads>>>(Wv, wqkv + (size_t)2 * D_ * K2_);
    split_w_t<<<wt_grid, wt_threads>>>(Wo, (__half*)pwo);

    // 2. fused QKV projection (one launch)
    const int smem_gemm = N_STAGE * STAGE_BYTES;   // 96 KB
    cudaFuncSetAttribute(gemm_ms, cudaFuncAttributeMaxDynamicSharedMemorySize, smem_gemm);
    dim3 gqkv(3 * D_ / 128, M_ / 128);   // (24, 256)
    gemm_ms<<<gqkv, 256, smem_gemm>>>((const __half*)pxs, wqkv,
                                      (float*)pq, (float*)pk, (float*)pv, 1);

    // 3. tensor-core attention (emits fp16 split)
    cudaFuncSetAttribute(attn_tc, cudaFuncAttributeMaxDynamicSharedMemorySize, AT_SMEM);
    attn_tc<<<B_ * H_, 128, AT_SMEM>>>((const float*)pq, (const float*)pk,
                                       (const float*)pv, bias, (__half*)pats);

    // 4. output projection
    dim3 go(D_ / 128, M_ / 128);   // (8, 256)
    gemm_ms<<<go, 256, smem_gemm>>>((const __half*)pats, (const __half*)pwo,
                                    out, out, out, 0);
}

// round 10
// speedup vs baseline: 7.6329x; 1.7045x over previous
#include <cuda_runtime.h>
#include <cuda_fp16.h>
#include <cstdint>
#include <math.h>

// Problem constants
#define B_   512
#define L_   64
#define H_   16
#define DH_  64
#define D_   1024
#define M_   (B_ * L_)        // 32768
#define K1_  1024             // plain fp16 K
#define NT_  (K1_ / 64)       // 16 K-tiles of 64 halfs

// ---------------------------------------------------------------------------
// Scratch (__device__ globals — no allocations allowed)
// ---------------------------------------------------------------------------
__device__ __half g_xs  [(size_t)M_ * K1_];        // x fp16      [M, 1024]
__device__ __half g_ats [(size_t)M_ * K1_];        // attn fp16   [M, 1024]
__device__ __half g_wqkv[(size_t)3 * D_ * K1_];    // [Wq;Wk;Wv]^T fp16
__device__ __half g_wo  [(size_t)D_ * K1_];        // Wo^T fp16
__device__ float g_q[(size_t)B_ * H_ * L_ * DH_];  // [B,H,L,Dh] fp32
__device__ float g_k[(size_t)B_ * H_ * L_ * DH_];
__device__ float g_v[(size_t)B_ * H_ * L_ * DH_];

__device__ __forceinline__ __half2 split1(float v) {
    __half hi = __float2half_rn(v);
    __half lo = __float2half_rn(v - __half2float(hi));
    __half2 p; p.x = hi; p.y = lo; return p;
}

// ---------------------------------------------------------------------------
// fp32 -> fp16 row conversion (no split)
// ---------------------------------------------------------------------------
__global__ __launch_bounds__(256) void conv_rows(
    const float* __restrict__ in, __half* __restrict__ out, int n8)
{
    int i = blockIdx.x * blockDim.x + threadIdx.x;
    if (i >= n8) return;
    float4 a = ((const float4*)in)[2 * i];
    float4 b = ((const float4*)in)[2 * i + 1];
    union { uint4 u; __half2 p[4]; } pk;
    pk.p[0] = __floats2half2_rn(a.x, a.y);
    pk.p[1] = __floats2half2_rn(a.z, a.w);
    pk.p[2] = __floats2half2_rn(b.x, b.y);
    pk.p[3] = __floats2half2_rn(b.z, b.w);
    ((uint4*)out)[i] = pk.u;
}

// All 4 weights: W[1024,1024] -> Wt fp16 [n][k] (transpose + convert), fused.
__global__ __launch_bounds__(256) void conv_w_t(
    const float* __restrict__ W0, const float* __restrict__ W1,
    const float* __restrict__ W2, const float* __restrict__ W3,
    __half* __restrict__ O0, __half* __restrict__ O3)
{
    __shared__ float t[32][33];
    const int which = blockIdx.z;
    const float* W = (which == 0) ? W0 : (which == 1) ? W1 : (which == 2) ? W2 : W3;
    __half* Wt = (which == 3) ? O3 : (O0 + (size_t)which * D_ * K1_);

    const int bn = blockIdx.x, bk = blockIdx.y;
    const int tx = threadIdx.x, ty = threadIdx.y;   // 32 x 8
#pragma unroll
    for (int i = 0; i < 32; i += 8)
        t[ty + i][tx] = W[(size_t)(bk * 32 + ty + i) * D_ + bn * 32 + tx];
    __syncthreads();
#pragma unroll
    for (int i = 0; i < 32; i += 8) {
        int n = bn * 32 + ty + i;
        int k = bk * 32 + tx;
        Wt[(size_t)n * K1_ + k] = __float2half_rn(t[tx][ty + i]);
    }
}

// ---------------------------------------------------------------------------
// HMMA GEMM, 3-stage cp.async pipeline, K=1024.
// mode 0: C0[M,1024] row-major.  mode 1: fused QKV scatter to [B,H,L,Dh].
// ---------------------------------------------------------------------------
#define STAGE_BYTES 32768
#define SMEM_B_OFF  16384
#define N_STAGE     3

__device__ __forceinline__ uint32_t smem_u32(const void* p) {
    uint32_t a;
    asm("{ .reg .u64 t; cvta.to.shared.u64 t, %1; cvt.u32.u64 %0, t; }"
        : "=r"(a) : "l"(p));
    return a;
}

__device__ __forceinline__ void cp16(uint32_t dst, const void* src) {
    asm volatile("cp.async.cg.shared.global [%0], [%1], 16;\n"
                 :: "r"(dst), "l"(src));
}

__global__ __launch_bounds__(256) void gemm_ms(
    const __half* __restrict__ A,
    const __half* __restrict__ Bt,
    float* __restrict__ C0, float* __restrict__ C1, float* __restrict__ C2,
    int mode)
{
    extern __shared__ char smem[];
    const uint32_t sbase = smem_u32(smem);
    const int tid = threadIdx.x;
    const int wid = tid >> 5;
    const int lid = tid & 31;
    const int wm  = wid >> 2;
    const int wn  = wid & 3;
    const int nb = blockIdx.x;
    const int mb = blockIdx.y;

    const __half* Ab = A  + (size_t)(mb * 128) * K1_;
    const __half* Bb = Bt + (size_t)(nb * 128) * K1_;

    uint32_t soff[4]; int lr[4], lc[4];
#pragma unroll
    for (int i = 0; i < 4; i++) {
        int idx = i * 256 + tid;
        int r = idx >> 3, c = idx & 7;
        lr[i] = r; lc[i] = c;
        soff[i] = (uint32_t)(r * 128 + (c ^ (r & 7)) * 16);
    }

    float acc[4][4][4];
#pragma unroll
    for (int mi = 0; mi < 4; mi++)
#pragma unroll
        for (int ni = 0; ni < 4; ni++)
#pragma unroll
            for (int e = 0; e < 4; e++) acc[mi][ni][e] = 0.0f;

    const int a_row = wm * 64 + (lid & 15);
    const int a_kh  = lid >> 4;
    const int b_row = wn * 32 + ((lid >> 4) * 8) + (lid & 7);
    const int b_kh  = (lid >> 3) & 1;

#pragma unroll
    for (int s = 0; s < 2; s++) {
        const uint32_t st = sbase + s * STAGE_BYTES;
        const int k0 = s * 64;
#pragma unroll
        for (int i = 0; i < 4; i++) {
            cp16(st + soff[i],              Ab + (size_t)lr[i] * K1_ + k0 + lc[i] * 8);
            cp16(st + SMEM_B_OFF + soff[i], Bb + (size_t)lr[i] * K1_ + k0 + lc[i] * 8);
        }
        asm volatile("cp.async.commit_group;\n");
    }

    int cm_stage = 0;
    int ld_stage = 2;

    for (int it = 0; it < NT_; ++it) {
        if (it + 1 < NT_) asm volatile("cp.async.wait_group 1;\n");
        else              asm volatile("cp.async.wait_group 0;\n");
        __syncthreads();

        if (it + 2 < NT_) {
            const uint32_t st = sbase + ld_stage * STAGE_BYTES;
            const int k0 = (it + 2) * 64;
#pragma unroll
            for (int i = 0; i < 4; i++) {
                cp16(st + soff[i],              Ab + (size_t)lr[i] * K1_ + k0 + lc[i] * 8);
                cp16(st + SMEM_B_OFF + soff[i], Bb + (size_t)lr[i] * K1_ + k0 + lc[i] * 8);
            }
            asm volatile("cp.async.commit_group;\n");
            if (++ld_stage == N_STAGE) ld_stage = 0;
        }

        const uint32_t sa = sbase + cm_stage * STAGE_BYTES;
        const uint32_t sb = sa + SMEM_B_OFF;
        if (++cm_stage == N_STAGE) cm_stage = 0;

#pragma unroll
        for (int k16 = 0; k16 < 4; k16++) {
            uint32_t af[4][4];
#pragma unroll
            for (int mi = 0; mi < 4; mi++) {
                int row = a_row + mi * 16;
                int ch  = (k16 * 2 + a_kh) ^ (row & 7);
                uint32_t ad = sa + row * 128 + ch * 16;
                asm volatile(
                    "ldmatrix.sync.aligned.m8n8.x4.shared.b16 {%0,%1,%2,%3}, [%4];"
                    : "=r"(af[mi][0]), "=r"(af[mi][1]), "=r"(af[mi][2]), "=r"(af[mi][3])
                    : "r"(ad));
            }
            uint32_t bf[4][2];
#pragma unroll
            for (int nj = 0; nj < 2; nj++) {
                int row = b_row + nj * 16;
                int ch  = (k16 * 2 + b_kh) ^ (row & 7);
                uint32_t bd = sb + row * 128 + ch * 16;
                uint32_t r0, r1, r2, r3;
                asm volatile(
                    "ldmatrix.sync.aligned.m8n8.x4.shared.b16 {%0,%1,%2,%3}, [%4];"
                    : "=r"(r0), "=r"(r1), "=r"(r2), "=r"(r3)
                    : "r"(bd));
                bf[nj * 2 + 0][0] = r0; bf[nj * 2 + 0][1] = r1;
                bf[nj * 2 + 1][0] = r2; bf[nj * 2 + 1][1] = r3;
            }
#pragma unroll
            for (int mi = 0; mi < 4; mi++)
#pragma unroll
                for (int ni = 0; ni < 4; ni++) {
                    asm volatile(
                        "mma.sync.aligned.m16n8k16.row.col.f32.f16.f16.f32 "
                        "{%0,%1,%2,%3}, {%4,%5,%6,%7}, {%8,%9}, {%0,%1,%2,%3};"
                        : "+f"(acc[mi][ni][0]), "+f"(acc[mi][ni][1]),
                          "+f"(acc[mi][ni][2]), "+f"(acc[mi][ni][3])
                        : "r"(af[mi][0]), "r"(af[mi][1]), "r"(af[mi][2]), "r"(af[mi][3]),
                          "r"(bf[ni][0]), "r"(bf[ni][1]));
                }
        }
    }

    // Epilogue
    float* Cs;
    int nbase;
    if (mode == 0) {
        Cs = C0;
        nbase = nb * 128;
    } else {
        const int which = nb >> 3;
        Cs = (which == 0) ? C0 : (which == 1) ? C1 : C2;
        nbase = (nb & 7) * 128;
    }

    const int tq = lid >> 2;
    const int tr = lid & 3;
#pragma unroll
    for (int mi = 0; mi < 4; mi++) {
#pragma unroll
        for (int half_ = 0; half_ < 2; half_++) {
            int m = mb * 128 + wm * 64 + mi * 16 + tq + half_ * 8;
#pragma unroll
            for (int ni = 0; ni < 4; ni++) {
                int n = nbase + wn * 32 + ni * 8 + tr * 2;
                float2 v;
                v.x = acc[mi][ni][half_ * 2 + 0];
                v.y = acc[mi][ni][half_ * 2 + 1];
                if (mode == 0) {
                    *(float2*)(Cs + (size_t)m * D_ + n) = v;
                } else {
                    int bb = m >> 6, ll = m & 63;
                    int h  = n >> 6, dh = n & 63;
                    *(float2*)(Cs + (((size_t)(bb * H_ + h) * L_ + ll) * DH_ + dh)) = v;
                }
            }
        }
    }
}

// ---------------------------------------------------------------------------
// Tensor-core attention (validated R7). Epilogue now plain fp16 [M,1024].
// ---------------------------------------------------------------------------
#define QK_ROWB 400
#define V_ROWB  144
#define AT_QS   0
#define AT_KS   (64 * QK_ROWB)
#define AT_VS   (2 * 64 * QK_ROWB)
#define AT_SMEM (AT_VS + 128 * V_ROWB)  // 69632

__global__ __launch_bounds__(128, 3) void attn_tc(
    const float* __restrict__ gq, const float* __restrict__ gk,
    const float* __restrict__ gv, const float* __restrict__ gbias,
    __half* __restrict__ gout)
{
    extern __shared__ char smc[];
    const uint32_t sb = smem_u32(smc);
    const int tid = threadIdx.x;
    const int wid = tid >> 5;
    const int lid = tid & 31;
    const int bh  = blockIdx.x;
    const int b   = bh >> 4;
    const int h   = bh & 15;
    const size_t base = (size_t)bh * (L_ * DH_);

#pragma unroll
    for (int it = 0; it < 8; it++) {
        int e   = it * 128 + tid;
        int row = e >> 4;
        int c4  = e & 15;
        float4 q4 = *(const float4*)(gq + base + row * 64 + c4 * 4);
        float4 k4 = *(const float4*)(gk + base + row * 64 + c4 * 4);
        float4 v4 = *(const float4*)(gv + base + row * 64 + c4 * 4);
        const float qv[4] = {q4.x, q4.y, q4.z, q4.w};
        const float kv[4] = {k4.x, k4.y, k4.z, k4.w};
        union { uint2 u[3]; __half hh[12]; } uq, uk;
#pragma unroll
        for (int e4 = 0; e4 < 4; e4++) {
            __half2 qs = split1(qv[e4]);
            __half  kh = __float2half_rn(kv[e4]);
            __half  kl = __float2half_rn(kv[e4] - __half2float(kh));
            uq.hh[3 * e4 + 0] = qs.x; uq.hh[3 * e4 + 1] = qs.y; uq.hh[3 * e4 + 2] = qs.x;
            uk.hh[3 * e4 + 0] = kh;   uk.hh[3 * e4 + 1] = kh;   uk.hh[3 * e4 + 2] = kl;
        }
        char* qp = smc + AT_QS + row * QK_ROWB + c4 * 24;
        char* kp = smc + AT_KS + row * QK_ROWB + c4 * 24;
#pragma unroll
        for (int u = 0; u < 3; u++) {
            *(uint2*)(qp + u * 8) = uq.u[u];
            *(uint2*)(kp + u * 8) = uk.u[u];
        }
        union { uint2 u; __half hh[4]; } uv;
        uv.hh[0] = __float2half_rn(v4.x); uv.hh[1] = __float2half_rn(v4.y);
        uv.hh[2] = __float2half_rn(v4.z); uv.hh[3] = __float2half_rn(v4.w);
        *(uint2*)(smc + AT_VS + (2 * row + 0) * V_ROWB + c4 * 8) = uv.u;
        *(uint2*)(smc + AT_VS + (2 * row + 1) * V_ROWB + c4 * 8) = uv.u;
    }
    __syncthreads();

    float SA[8][4];
#pragma unroll
    for (int j = 0; j < 8; j++)
#pragma unroll
        for (int e = 0; e < 4; e++) SA[j][e] = 0.0f;

    const uint32_t a_addr0 = sb + AT_QS + (wid * 16 + (lid & 15)) * QK_ROWB + (lid >> 4) * 16;
    const uint32_t b_rowsel = ((lid >> 4) * 8) + (lid & 7);
    const uint32_t b_khalf  = ((lid >> 3) & 1) * 16;

#pragma unroll
    for (int t = 0; t < 12; t++) {
        uint32_t a0, a1, a2, a3;
        asm volatile(
            "ldmatrix.sync.aligned.m8n8.x4.shared.b16 {%0,%1,%2,%3}, [%4];"
            : "=r"(a0), "=r"(a1), "=r"(a2), "=r"(a3)
            : "r"(a_addr0 + t * 32));
#pragma unroll
        for (int np = 0; np < 4; np++) {
            uint32_t b0, b1, b2, b3;
            uint32_t bd = sb + AT_KS + (np * 16 + b_rowsel) * QK_ROWB + t * 32 + b_khalf;
            asm volatile(
                "ldmatrix.sync.aligned.m8n8.x4.shared.b16 {%0,%1,%2,%3}, [%4];"
                : "=r"(b0), "=r"(b1), "=r"(b2), "=r"(b3)
                : "r"(bd));
            asm volatile(
                "mma.sync.aligned.m16n8k16.row.col.f32.f16.f16.f32 "
                "{%0,%1,%2,%3}, {%4,%5,%6,%7}, {%8,%9}, {%0,%1,%2,%3};"
                : "+f"(SA[2 * np][0]), "+f"(SA[2 * np][1]),
                  "+f"(SA[2 * np][2]), "+f"(SA[2 * np][3])
                : "r"(a0), "r"(a1), "r"(a2), "r"(a3), "r"(b0), "r"(b1));
            asm volatile(
                "mma.sync.aligned.m16n8k16.row.col.f32.f16.f16.f32 "
                "{%0,%1,%2,%3}, {%4,%5,%6,%7}, {%8,%9}, {%0,%1,%2,%3};"
                : "+f"(SA[2 * np + 1][0]), "+f"(SA[2 * np + 1][1]),
                  "+f"(SA[2 * np + 1][2]), "+f"(SA[2 * np + 1][3])
                : "r"(a0), "r"(a1), "r"(a2), "r"(a3), "r"(b2), "r"(b3));
        }
    }

    const int r = lid >> 2;
    const int c = lid & 3;
    const int qr = wid * 16 + r;
    const float* bp0 = gbias + (size_t)h * 4096 + qr * 64;
    const float* bp8 = bp0 + 8 * 64;

    float mx0 = -1e30f, mx8 = -1e30f;
#pragma unroll
    for (int j = 0; j < 8; j++) {
        float2 bb0 = *(const float2*)(bp0 + 8 * j + 2 * c);
        float2 bb8 = *(const float2*)(bp8 + 8 * j + 2 * c);
        SA[j][0] = SA[j][0] * 0.125f + bb0.x;
        SA[j][1] = SA[j][1] * 0.125f + bb0.y;
        SA[j][2] = SA[j][2] * 0.125f + bb8.x;
        SA[j][3] = SA[j][3] * 0.125f + bb8.y;
        mx0 = fmaxf(mx0, fmaxf(SA[j][0], SA[j][1]));
        mx8 = fmaxf(mx8, fmaxf(SA[j][2], SA[j][3]));
    }
    mx0 = fmaxf(mx0, __shfl_xor_sync(0xffffffffu, mx0, 1));
    mx0 = fmaxf(mx0, __shfl_xor_sync(0xffffffffu, mx0, 2));
    mx8 = fmaxf(mx8, __shfl_xor_sync(0xffffffffu, mx8, 1));
    mx8 = fmaxf(mx8, __shfl_xor_sync(0xffffffffu, mx8, 2));

    float s0 = 0.0f, s8 = 0.0f;
#pragma unroll
    for (int j = 0; j < 8; j++) {
        SA[j][0] = __expf(SA[j][0] - mx0); s0 += SA[j][0];
        SA[j][1] = __expf(SA[j][1] - mx0); s0 += SA[j][1];
        SA[j][2] = __expf(SA[j][2] - mx8); s8 += SA[j][2];
        SA[j][3] = __expf(SA[j][3] - mx8); s8 += SA[j][3];
    }
    s0 += __shfl_xor_sync(0xffffffffu, s0, 1);
    s0 += __shfl_xor_sync(0xffffffffu, s0, 2);
    s8 += __shfl_xor_sync(0xffffffffu, s8, 1);
    s8 += __shfl_xor_sync(0xffffffffu, s8, 2);
    const float inv0 = 1.0f / s0, inv8 = 1.0f / s8;
#pragma unroll
    for (int j = 0; j < 8; j++) {
        SA[j][0] *= inv0; SA[j][1] *= inv0;
        SA[j][2] *= inv8; SA[j][3] *= inv8;
    }

    float OA[8][4];
#pragma unroll
    for (int j = 0; j < 8; j++)
#pragma unroll
        for (int e = 0; e < 4; e++) OA[j][e] = 0.0f;

    const int l1 = (lid & ~3) | (c >> 1);
    const int l2 = l1 + 2;
    const int selb = c & 1;
    const uint32_t v_row = (lid & 7) + 8 * ((lid >> 3) & 1);
    const uint32_t v_col = ((lid >> 4) * 8) * 2;

#pragma unroll
    for (int t = 0; t < 8; t++) {
        float s00 = __shfl_sync(0xffffffffu, SA[t][0], l1);
        float s01 = __shfl_sync(0xffffffffu, SA[t][1], l1);
        float s02 = __shfl_sync(0xffffffffu, SA[t][2], l1);
        float s03 = __shfl_sync(0xffffffffu, SA[t][3], l1);
        float s10 = __shfl_sync(0xffffffffu, SA[t][0], l2);
        float s11 = __shfl_sync(0xffffffffu, SA[t][1], l2);
        float s12 = __shfl_sync(0xffffffffu, SA[t][2], l2);
        float s13 = __shfl_sync(0xffffffffu, SA[t][3], l2);
        float v0 = selb ? s01 : s00;
        float v1 = selb ? s03 : s02;
        float v2 = selb ? s11 : s10;
        float v3 = selb ? s13 : s12;
        union { uint32_t u; __half2 p; } a0, a1, a2, a3;
        a0.p = split1(v0); a1.p = split1(v1);
        a2.p = split1(v2); a3.p = split1(v3);

#pragma unroll
        for (int dp = 0; dp < 4; dp++) {
            uint32_t bd = sb + AT_VS + (16 * t + v_row) * V_ROWB + dp * 32 + v_col;
            uint32_t b0, b1, b2, b3;
            asm volatile(
                "ldmatrix.sync.aligned.m8n8.x4.trans.shared.b16 {%0,%1,%2,%3}, [%4];"
                : "=r"(b0), "=r"(b1), "=r"(b2), "=r"(b3)
                : "r"(bd));
            asm volatile(
                "mma.sync.aligned.m16n8k16.row.col.f32.f16.f16.f32 "
                "{%0,%1,%2,%3}, {%4,%5,%6,%7}, {%8,%9}, {%0,%1,%2,%3};"
                : "+f"(OA[2 * dp][0]), "+f"(OA[2 * dp][1]),
                  "+f"(OA[2 * dp][2]), "+f"(OA[2 * dp][3])
                : "r"(a0.u), "r"(a1.u), "r"(a2.u), "r"(a3.u), "r"(b0), "r"(b1));
            asm volatile(
                "mma.sync.aligned.m16n8k16.row.col.f32.f16.f16.f32 "
                "{%0,%1,%2,%3}, {%4,%5,%6,%7}, {%8,%9}, {%0,%1,%2,%3};"
                : "+f"(OA[2 * dp + 1][0]), "+f"(OA[2 * dp + 1][1]),
                  "+f"(OA[2 * dp + 1][2]), "+f"(OA[2 * dp + 1][3])
                : "r"(a0.u), "r"(a1.u), "r"(a2.u), "r"(a3.u), "r"(b2), "r"(b3));
        }
    }

    // plain fp16 epilogue into [M,1024]
    const int m = b * 64 + qr;
#pragma unroll
    for (int j = 0; j < 8; j++) {
        int d = 8 * j + 2 * c;
        size_t col = (size_t)(h * 64 + d);
        union { uint32_t u; __half2 p; } w;
        w.p = __floats2half2_rn(OA[j][0], OA[j][1]);
        *(uint32_t*)(gout + (size_t)m * K1_ + col) = w.u;
        w.p = __floats2half2_rn(OA[j][2], OA[j][3]);
        *(uint32_t*)(gout + (size_t)(m + 8) * K1_ + col) = w.u;
    }
}

// ---------------------------------------------------------------------------
// Launch
// ---------------------------------------------------------------------------
extern "C" void kernel_launch(void* const* d_in, const int* in_sizes, int n_in,
                              void* d_out, int out_size)
{
    const float* x    = (const float*)d_in[0];
    const float* bias = (const float*)d_in[1];
    const float* Wq   = (const float*)d_in[2];
    const float* Wk   = (const float*)d_in[3];
    const float* Wv   = (const float*)d_in[4];
    const float* Wo   = (const float*)d_in[5];
    float* out = (float*)d_out;

    void *pxs, *pats, *pwqkv, *pwo, *pq, *pk, *pv;
    cudaGetSymbolAddress(&pxs,   g_xs);
    cudaGetSymbolAddress(&pats,  g_ats);
    cudaGetSymbolAddress(&pwqkv, g_wqkv);
    cudaGetSymbolAddress(&pwo,   g_wo);
    cudaGetSymbolAddress(&pq,    g_q);
    cudaGetSymbolAddress(&pk,    g_k);
    cudaGetSymbolAddress(&pv,    g_v);

    // 1. convert inputs to fp16
    conv_rows<<<(M_ * D_ / 8 + 255) / 256, 256>>>(x, (__half*)pxs, M_ * D_ / 8);
    dim3 wt_threads(32, 8), wt_grid(32, 32, 4);
    conv_w_t<<<wt_grid, wt_threads>>>(Wq, Wk, Wv, Wo, (__half*)pwqkv, (__half*)pwo);

    // 2. fused QKV projection (one launch)
    const int smem_gemm = N_STAGE * STAGE_BYTES;   // 96 KB
    cudaFuncSetAttribute(gemm_ms, cudaFuncAttributeMaxDynamicSharedMemorySize, smem_gemm);
    dim3 gqkv(3 * D_ / 128, M_ / 128);   // (24, 256)
    gemm_ms<<<gqkv, 256, smem_gemm>>>((const __half*)pxs, (const __half*)pwqkv,
                                      (float*)pq, (float*)pk, (float*)pv, 1);

    // 3. tensor-core attention (emits fp16)
    cudaFuncSetAttribute(attn_tc, cudaFuncAttributeMaxDynamicSharedMemorySize, AT_SMEM);
    attn_tc<<<B_ * H_, 128, AT_SMEM>>>((const float*)pq, (const float*)pk,
                                       (const float*)pv, bias, (__half*)pats);

    // 4. output projection
    dim3 go(D_ / 128, M_ / 128);   // (8, 256)
    gemm_ms<<<go, 256, smem_gemm>>>((const __half*)pats, (const __half*)pwo,
                                    out, out, out, 0);
}

// round 12
// speedup vs baseline: 7.6649x; 1.0042x over previous
#include <cuda_runtime.h>
#include <cuda_fp16.h>
#include <cstdint>
#include <math.h>

// Problem constants
#define B_   512
#define L_   64
#define H_   16
#define DH_  64
#define D_   1024
#define M_   (B_ * L_)        // 32768
#define K1_  1024             // plain fp16 K
#define NT_  (K1_ / 64)       // 16 K-tiles of 64 halfs

// ---------------------------------------------------------------------------
// Scratch (__device__ globals — no allocations allowed)
// ---------------------------------------------------------------------------
__device__ __half g_xs  [(size_t)M_ * K1_];        // x fp16      [M, 1024]
__device__ __half g_ats [(size_t)M_ * K1_];        // attn fp16   [M, 1024]
__device__ __half g_wqkv[(size_t)3 * D_ * K1_];    // [Wq;Wk;Wv]^T fp16
__device__ __half g_wo  [(size_t)D_ * K1_];        // Wo^T fp16
__device__ float  g_qk  [(size_t)M_ * 2048];       // [M, 2048]: Q | K  (fp32, row-major)
__device__ __half g_vh  [(size_t)M_ * 1024];       // [M, 1024]: V fp16 row-major

__device__ __forceinline__ __half2 split1(float v) {
    __half hi = __float2half_rn(v);
    __half lo = __float2half_rn(v - __half2float(hi));
    __half2 p; p.x = hi; p.y = lo; return p;
}

// ---------------------------------------------------------------------------
// fp32 -> fp16 row conversion
// ---------------------------------------------------------------------------
__global__ __launch_bounds__(256) void conv_rows(
    const float* __restrict__ in, __half* __restrict__ out, int n8)
{
    int i = blockIdx.x * blockDim.x + threadIdx.x;
    if (i >= n8) return;
    float4 a = ((const float4*)in)[2 * i];
    float4 b = ((const float4*)in)[2 * i + 1];
    union { uint4 u; __half2 p[4]; } pk;
    pk.p[0] = __floats2half2_rn(a.x, a.y);
    pk.p[1] = __floats2half2_rn(a.z, a.w);
    pk.p[2] = __floats2half2_rn(b.x, b.y);
    pk.p[3] = __floats2half2_rn(b.z, b.w);
    ((uint4*)out)[i] = pk.u;
}

// All 4 weights: W[1024,1024] -> Wt fp16 [n][k] (transpose + convert), fused.
__global__ __launch_bounds__(256) void conv_w_t(
    const float* __restrict__ W0, const float* __restrict__ W1,
    const float* __restrict__ W2, const float* __restrict__ W3,
    __half* __restrict__ O0, __half* __restrict__ O3)
{
    __shared__ float t[32][33];
    const int which = blockIdx.z;
    const float* W = (which == 0) ? W0 : (which == 1) ? W1 : (which == 2) ? W2 : W3;
    __half* Wt = (which == 3) ? O3 : (O0 + (size_t)which * D_ * K1_);

    const int bn = blockIdx.x, bk = blockIdx.y;
    const int tx = threadIdx.x, ty = threadIdx.y;   // 32 x 8
#pragma unroll
    for (int i = 0; i < 32; i += 8)
        t[ty + i][tx] = W[(size_t)(bk * 32 + ty + i) * D_ + bn * 32 + tx];
    __syncthreads();
#pragma unroll
    for (int i = 0; i < 32; i += 8) {
        int n = bn * 32 + ty + i;
        int k = bk * 32 + tx;
        Wt[(size_t)n * K1_ + k] = __float2half_rn(t[tx][ty + i]);
    }
}

// ---------------------------------------------------------------------------
// HMMA GEMM, 3-stage cp.async pipeline, K=1024.
// mode 0: C[M,1024] fp32 row-major.
// mode 1: fused QKV, N=3072. n<2048 -> C[m*2048+n] fp32 (Q|K);
//         n>=2048 -> Vh[m*1024 + n-2048] fp16. All row-major coalesced.
// ---------------------------------------------------------------------------
#define STAGE_BYTES 32768
#define SMEM_B_OFF  16384
#define N_STAGE     3

__device__ __forceinline__ uint32_t smem_u32(const void* p) {
    uint32_t a;
    asm("{ .reg .u64 t; cvta.to.shared.u64 t, %1; cvt.u32.u64 %0, t; }"
        : "=r"(a) : "l"(p));
    return a;
}

__device__ __forceinline__ void cp16(uint32_t dst, const void* src) {
    asm volatile("cp.async.cg.shared.global [%0], [%1], 16;\n"
                 :: "r"(dst), "l"(src));
}

__global__ __launch_bounds__(256) void gemm_ms(
    const __half* __restrict__ A,
    const __half* __restrict__ Bt,
    float* __restrict__ C, __half* __restrict__ Vh,
    int mode)
{
    extern __shared__ char smem[];
    const uint32_t sbase = smem_u32(smem);
    const int tid = threadIdx.x;
    const int wid = tid >> 5;
    const int lid = tid & 31;
    const int wm  = wid >> 2;
    const int wn  = wid & 3;
    const int nb = blockIdx.x;
    const int mb = blockIdx.y;

    const __half* Ab = A  + (size_t)(mb * 128) * K1_;
    const __half* Bb = Bt + (size_t)(nb * 128) * K1_;

    uint32_t soff[4]; int lr[4], lc[4];
#pragma unroll
    for (int i = 0; i < 4; i++) {
        int idx = i * 256 + tid;
        int r = idx >> 3, c = idx & 7;
        lr[i] = r; lc[i] = c;
        soff[i] = (uint32_t)(r * 128 + (c ^ (r & 7)) * 16);
    }

    float acc[4][4][4];
#pragma unroll
    for (int mi = 0; mi < 4; mi++)
#pragma unroll
        for (int ni = 0; ni < 4; ni++)
#pragma unroll
            for (int e = 0; e < 4; e++) acc[mi][ni][e] = 0.0f;

    const int a_row = wm * 64 + (lid & 15);
    const int a_kh  = lid >> 4;
    const int b_row = wn * 32 + ((lid >> 4) * 8) + (lid & 7);
    const int b_kh  = (lid >> 3) & 1;

#pragma unroll
    for (int s = 0; s < 2; s++) {
        const uint32_t st = sbase + s * STAGE_BYTES;
        const int k0 = s * 64;
#pragma unroll
        for (int i = 0; i < 4; i++) {
            cp16(st + soff[i],              Ab + (size_t)lr[i] * K1_ + k0 + lc[i] * 8);
            cp16(st + SMEM_B_OFF + soff[i], Bb + (size_t)lr[i] * K1_ + k0 + lc[i] * 8);
        }
        asm volatile("cp.async.commit_group;\n");
    }

    int cm_stage = 0;
    int ld_stage = 2;

    for (int it = 0; it < NT_; ++it) {
        if (it + 1 < NT_) asm volatile("cp.async.wait_group 1;\n");
        else              asm volatile("cp.async.wait_group 0;\n");
        __syncthreads();

        if (it + 2 < NT_) {
            const uint32_t st = sbase + ld_stage * STAGE_BYTES;
            const int k0 = (it + 2) * 64;
#pragma unroll
            for (int i = 0; i < 4; i++) {
                cp16(st + soff[i],              Ab + (size_t)lr[i] * K1_ + k0 + lc[i] * 8);
                cp16(st + SMEM_B_OFF + soff[i], Bb + (size_t)lr[i] * K1_ + k0 + lc[i] * 8);
            }
            asm volatile("cp.async.commit_group;\n");
            if (++ld_stage == N_STAGE) ld_stage = 0;
        }

        const uint32_t sa = sbase + cm_stage * STAGE_BYTES;
        const uint32_t sb = sa + SMEM_B_OFF;
        if (++cm_stage == N_STAGE) cm_stage = 0;

#pragma unroll
        for (int k16 = 0; k16 < 4; k16++) {
            uint32_t af[4][4];
#pragma unroll
            for (int mi = 0; mi < 4; mi++) {
                int row = a_row + mi * 16;
                int ch  = (k16 * 2 + a_kh) ^ (row & 7);
                uint32_t ad = sa + row * 128 + ch * 16;
                asm volatile(
                    "ldmatrix.sync.aligned.m8n8.x4.shared.b16 {%0,%1,%2,%3}, [%4];"
                    : "=r"(af[mi][0]), "=r"(af[mi][1]), "=r"(af[mi][2]), "=r"(af[mi][3])
                    : "r"(ad));
            }
            uint32_t bf[4][2];
#pragma unroll
            for (int nj = 0; nj < 2; nj++) {
                int row = b_row + nj * 16;
                int ch  = (k16 * 2 + b_kh) ^ (row & 7);
                uint32_t bd = sb + row * 128 + ch * 16;
                uint32_t r0, r1, r2, r3;
                asm volatile(
                    "ldmatrix.sync.aligned.m8n8.x4.shared.b16 {%0,%1,%2,%3}, [%4];"
                    : "=r"(r0), "=r"(r1), "=r"(r2), "=r"(r3)
                    : "r"(bd));
                bf[nj * 2 + 0][0] = r0; bf[nj * 2 + 0][1] = r1;
                bf[nj * 2 + 1][0] = r2; bf[nj * 2 + 1][1] = r3;
            }
#pragma unroll
            for (int mi = 0; mi < 4; mi++)
#pragma unroll
                for (int ni = 0; ni < 4; ni++) {
                    asm volatile(
                        "mma.sync.aligned.m16n8k16.row.col.f32.f16.f16.f32 "
                        "{%0,%1,%2,%3}, {%4,%5,%6,%7}, {%8,%9}, {%0,%1,%2,%3};"
                        : "+f"(acc[mi][ni][0]), "+f"(acc[mi][ni][1]),
                          "+f"(acc[mi][ni][2]), "+f"(acc[mi][ni][3])
                        : "r"(af[mi][0]), "r"(af[mi][1]), "r"(af[mi][2]), "r"(af[mi][3]),
                          "r"(bf[ni][0]), "r"(bf[ni][1]));
                }
        }
    }

    // Epilogue (all row-major)
    const int nbase = nb * 128;
    const int tq = lid >> 2;
    const int tr = lid & 3;
#pragma unroll
    for (int mi = 0; mi < 4; mi++) {
#pragma unroll
        for (int half_ = 0; half_ < 2; half_++) {
            int m = mb * 128 + wm * 64 + mi * 16 + tq + half_ * 8;
#pragma unroll
            for (int ni = 0; ni < 4; ni++) {
                int n = nbase + wn * 32 + ni * 8 + tr * 2;
                float vx = acc[mi][ni][half_ * 2 + 0];
                float vy = acc[mi][ni][half_ * 2 + 1];
                if (mode == 0) {
                    *(float2*)(C + (size_t)m * 1024 + n) = make_float2(vx, vy);
                } else if (n < 2048) {
                    *(float2*)(C + (size_t)m * 2048 + n) = make_float2(vx, vy);
                } else {
                    union { uint32_t u; __half2 p; } w;
                    w.p = __floats2half2_rn(vx, vy);
                    *(uint32_t*)(Vh + (size_t)m * 1024 + (n - 2048)) = w.u;
                }
            }
        }
    }
}

// ---------------------------------------------------------------------------
// Tensor-core attention: one block per (b,h), 4 warps x 16 Q-rows.
// Reads Q,K fp32 from g_qk [M,2048] (coalesced gather), V fp16 from g_vh.
// ---------------------------------------------------------------------------
#define QK_ROWB 400
#define V_ROWB  144
#define AT_QS   0
#define AT_KS   (64 * QK_ROWB)
#define AT_VS   (2 * 64 * QK_ROWB)
#define AT_SMEM (AT_VS + 128 * V_ROWB)  // 69632

__global__ __launch_bounds__(128, 3) void attn_tc(
    const float* __restrict__ gqk, const __half* __restrict__ gvh,
    const float* __restrict__ gbias, __half* __restrict__ gout)
{
    extern __shared__ char smc[];
    const uint32_t sb = smem_u32(smc);
    const int tid = threadIdx.x;
    const int wid = tid >> 5;
    const int lid = tid & 31;
    const int bh  = blockIdx.x;
    const int b   = bh >> 4;
    const int h   = bh & 15;

    // ---- load + convert Q,K (fp32) and V (fp16) into smem ----
#pragma unroll
    for (int it = 0; it < 8; it++) {
        int e   = it * 128 + tid;     // 0..1023
        int row = e >> 4;
        int c4  = e & 15;
        const size_t mrow = (size_t)(b * 64 + row);
        float4 q4 = *(const float4*)(gqk + mrow * 2048 + h * 64 + c4 * 4);
        float4 k4 = *(const float4*)(gqk + mrow * 2048 + 1024 + h * 64 + c4 * 4);
        uint2  v2 = *(const uint2*) (gvh + mrow * 1024 + h * 64 + c4 * 4);
        const float qv[4] = {q4.x, q4.y, q4.z, q4.w};
        const float kv[4] = {k4.x, k4.y, k4.z, k4.w};
        union { uint2 u[3]; __half hh[12]; } uq, uk;
#pragma unroll
        for (int e4 = 0; e4 < 4; e4++) {
            __half2 qs = split1(qv[e4]);
            __half  kh = __float2half_rn(kv[e4]);
            __half  kl = __float2half_rn(kv[e4] - __half2float(kh));
            uq.hh[3 * e4 + 0] = qs.x; uq.hh[3 * e4 + 1] = qs.y; uq.hh[3 * e4 + 2] = qs.x;
            uk.hh[3 * e4 + 0] = kh;   uk.hh[3 * e4 + 1] = kh;   uk.hh[3 * e4 + 2] = kl;
        }
        char* qp = smc + AT_QS + row * QK_ROWB + c4 * 24;
        char* kp = smc + AT_KS + row * QK_ROWB + c4 * 24;
#pragma unroll
        for (int u = 0; u < 3; u++) {
            *(uint2*)(qp + u * 8) = uq.u[u];
            *(uint2*)(kp + u * 8) = uk.u[u];
        }
        *(uint2*)(smc + AT_VS + (2 * row + 0) * V_ROWB + c4 * 8) = v2;
        *(uint2*)(smc + AT_VS + (2 * row + 1) * V_ROWB + c4 * 8) = v2;
    }
    __syncthreads();

    float SA[8][4];
#pragma unroll
    for (int j = 0; j < 8; j++)
#pragma unroll
        for (int e = 0; e < 4; e++) SA[j][e] = 0.0f;

    const uint32_t a_addr0 = sb + AT_QS + (wid * 16 + (lid & 15)) * QK_ROWB + (lid >> 4) * 16;
    const uint32_t b_rowsel = ((lid >> 4) * 8) + (lid & 7);
    const uint32_t b_khalf  = ((lid >> 3) & 1) * 16;

#pragma unroll
    for (int t = 0; t < 12; t++) {
        uint32_t a0, a1, a2, a3;
        asm volatile(
            "ldmatrix.sync.aligned.m8n8.x4.shared.b16 {%0,%1,%2,%3}, [%4];"
            : "=r"(a0), "=r"(a1), "=r"(a2), "=r"(a3)
            : "r"(a_addr0 + t * 32));
#pragma unroll
        for (int np = 0; np < 4; np++) {
            uint32_t b0, b1, b2, b3;
            uint32_t bd = sb + AT_KS + (np * 16 + b_rowsel) * QK_ROWB + t * 32 + b_khalf;
            asm volatile(
                "ldmatrix.sync.aligned.m8n8.x4.shared.b16 {%0,%1,%2,%3}, [%4];"
                : "=r"(b0), "=r"(b1), "=r"(b2), "=r"(b3)
                : "r"(bd));
            asm volatile(
                "mma.sync.aligned.m16n8k16.row.col.f32.f16.f16.f32 "
                "{%0,%1,%2,%3}, {%4,%5,%6,%7}, {%8,%9}, {%0,%1,%2,%3};"
                : "+f"(SA[2 * np][0]), "+f"(SA[2 * np][1]),
                  "+f"(SA[2 * np][2]), "+f"(SA[2 * np][3])
                : "r"(a0), "r"(a1), "r"(a2), "r"(a3), "r"(b0), "r"(b1));
            asm volatile(
                "mma.sync.aligned.m16n8k16.row.col.f32.f16.f16.f32 "
                "{%0,%1,%2,%3}, {%4,%5,%6,%7}, {%8,%9}, {%0,%1,%2,%3};"
                : "+f"(SA[2 * np + 1][0]), "+f"(SA[2 * np + 1][1]),
                  "+f"(SA[2 * np + 1][2]), "+f"(SA[2 * np + 1][3])
                : "r"(a0), "r"(a1), "r"(a2), "r"(a3), "r"(b2), "r"(b3));
        }
    }

    const int r = lid >> 2;
    const int c = lid & 3;
    const int qr = wid * 16 + r;
    const float* bp0 = gbias + (size_t)h * 4096 + qr * 64;
    const float* bp8 = bp0 + 8 * 64;

    float mx0 = -1e30f, mx8 = -1e30f;
#pragma unroll
    for (int j = 0; j < 8; j++) {
        float2 bb0 = *(const float2*)(bp0 + 8 * j + 2 * c);
        float2 bb8 = *(const float2*)(bp8 + 8 * j + 2 * c);
        SA[j][0] = SA[j][0] * 0.125f + bb0.x;
        SA[j][1] = SA[j][1] * 0.125f + bb0.y;
        SA[j][2] = SA[j][2] * 0.125f + bb8.x;
        SA[j][3] = SA[j][3] * 0.125f + bb8.y;
        mx0 = fmaxf(mx0, fmaxf(SA[j][0], SA[j][1]));
        mx8 = fmaxf(mx8, fmaxf(SA[j][2], SA[j][3]));
    }
    mx0 = fmaxf(mx0, __shfl_xor_sync(0xffffffffu, mx0, 1));
    mx0 = fmaxf(mx0, __shfl_xor_sync(0xffffffffu, mx0, 2));
    mx8 = fmaxf(mx8, __shfl_xor_sync(0xffffffffu, mx8, 1));
    mx8 = fmaxf(mx8, __shfl_xor_sync(0xffffffffu, mx8, 2));

    float s0 = 0.0f, s8 = 0.0f;
#pragma unroll
    for (int j = 0; j < 8; j++) {
        SA[j][0] = __expf(SA[j][0] - mx0); s0 += SA[j][0];
        SA[j][1] = __expf(SA[j][1] - mx0); s0 += SA[j][1];
        SA[j][2] = __expf(SA[j][2] - mx8); s8 += SA[j][2];
        SA[j][3] = __expf(SA[j][3] - mx8); s8 += SA[j][3];
    }
    s0 += __shfl_xor_sync(0xffffffffu, s0, 1);
    s0 += __shfl_xor_sync(0xffffffffu, s0, 2);
    s8 += __shfl_xor_sync(0xffffffffu, s8, 1);
    s8 += __shfl_xor_sync(0xffffffffu, s8, 2);
    const float inv0 = 1.0f / s0, inv8 = 1.0f / s8;
#pragma unroll
    for (int j = 0; j < 8; j++) {
        SA[j][0] *= inv0; SA[j][1] *= inv0;
        SA[j][2] *= inv8; SA[j][3] *= inv8;
    }

    float OA[8][4];
#pragma unroll
    for (int j = 0; j < 8; j++)
#pragma unroll
        for (int e = 0; e < 4; e++) OA[j][e] = 0.0f;

    const int l1 = (lid & ~3) | (c >> 1);
    const int l2 = l1 + 2;
    const int selb = c & 1;
    const uint32_t v_row = (lid & 7) + 8 * ((lid >> 3) & 1);
    const uint32_t v_col = ((lid >> 4) * 8) * 2;

#pragma unroll
    for (int t = 0; t < 8; t++) {
        float s00 = __shfl_sync(0xffffffffu, SA[t][0], l1);
        float s01 = __shfl_sync(0xffffffffu, SA[t][1], l1);
        float s02 = __shfl_sync(0xffffffffu, SA[t][2], l1);
        float s03 = __shfl_sync(0xffffffffu, SA[t][3], l1);
        float s10 = __shfl_sync(0xffffffffu, SA[t][0], l2);
        float s11 = __shfl_sync(0xffffffffu, SA[t][1], l2);
        float s12 = __shfl_sync(0xffffffffu, SA[t][2], l2);
        float s13 = __shfl_sync(0xffffffffu, SA[t][3], l2);
        float v0 = selb ? s01 : s00;
        float v1 = selb ? s03 : s02;
        float v2 = selb ? s11 : s10;
        float v3 = selb ? s13 : s12;
        union { uint32_t u; __half2 p; } a0, a1, a2, a3;
        a0.p = split1(v0); a1.p = split1(v1);
        a2.p = split1(v2); a3.p = split1(v3);

#pragma unroll
        for (int dp = 0; dp < 4; dp++) {
            uint32_t bd = sb + AT_VS + (16 * t + v_row) * V_ROWB + dp * 32 + v_col;
            uint32_t b0, b1, b2, b3;
            asm volatile(
                "ldmatrix.sync.aligned.m8n8.x4.trans.shared.b16 {%0,%1,%2,%3}, [%4];"
                : "=r"(b0), "=r"(b1), "=r"(b2), "=r"(b3)
                : "r"(bd));
            asm volatile(
                "mma.sync.aligned.m16n8k16.row.col.f32.f16.f16.f32 "
                "{%0,%1,%2,%3}, {%4,%5,%6,%7}, {%8,%9}, {%0,%1,%2,%3};"
                : "+f"(OA[2 * dp][0]), "+f"(OA[2 * dp][1]),
                  "+f"(OA[2 * dp][2]), "+f"(OA[2 * dp][3])
                : "r"(a0.u), "r"(a1.u), "r"(a2.u), "r"(a3.u), "r"(b0), "r"(b1));
            asm volatile(
                "mma.sync.aligned.m16n8k16.row.col.f32.f16.f16.f32 "
                "{%0,%1,%2,%3}, {%4,%5,%6,%7}, {%8,%9}, {%0,%1,%2,%3};"
                : "+f"(OA[2 * dp + 1][0]), "+f"(OA[2 * dp + 1][1]),
                  "+f"(OA[2 * dp + 1][2]), "+f"(OA[2 * dp + 1][3])
                : "r"(a0.u), "r"(a1.u), "r"(a2.u), "r"(a3.u), "r"(b2), "r"(b3));
        }
    }

    // plain fp16 epilogue into [M,1024]
    const int m = b * 64 + qr;
#pragma unroll
    for (int j = 0; j < 8; j++) {
        int d = 8 * j + 2 * c;
        size_t col = (size_t)(h * 64 + d);
        union { uint32_t u; __half2 p; } w;
        w.p = __floats2half2_rn(OA[j][0], OA[j][1]);
        *(uint32_t*)(gout + (size_t)m * K1_ + col) = w.u;
        w.p = __floats2half2_rn(OA[j][2], OA[j][3]);
        *(uint32_t*)(gout + (size_t)(m + 8) * K1_ + col) = w.u;
    }
}

// ---------------------------------------------------------------------------
// Launch
// ---------------------------------------------------------------------------
extern "C" void kernel_launch(void* const* d_in, const int* in_sizes, int n_in,
                              void* d_out, int out_size)
{
    const float* x    = (const float*)d_in[0];
    const float* bias = (const float*)d_in[1];
    const float* Wq   = (const float*)d_in[2];
    const float* Wk   = (const float*)d_in[3];
    const float* Wv   = (const float*)d_in[4];
    const float* Wo   = (const float*)d_in[5];
    float* out = (float*)d_out;

    void *pxs, *pats, *pwqkv, *pwo, *pqk, *pvh;
    cudaGetSymbolAddress(&pxs,   g_xs);
    cudaGetSymbolAddress(&pats,  g_ats);
    cudaGetSymbolAddress(&pwqkv, g_wqkv);
    cudaGetSymbolAddress(&pwo,   g_wo);
    cudaGetSymbolAddress(&pqk,   g_qk);
    cudaGetSymbolAddress(&pvh,   g_vh);

    // 1. convert inputs to fp16
    conv_rows<<<(M_ * D_ / 8 + 255) / 256, 256>>>(x, (__half*)pxs, M_ * D_ / 8);
    dim3 wt_threads(32, 8), wt_grid(32, 32, 4);
    conv_w_t<<<wt_grid, wt_threads>>>(Wq, Wk, Wv, Wo, (__half*)pwqkv, (__half*)pwo);

    // 2. fused QKV projection (one launch, row-major epilogue)
    const int smem_gemm = N_STAGE * STAGE_BYTES;   // 96 KB
    cudaFuncSetAttribute(gemm_ms, cudaFuncAttributeMaxDynamicSharedMemorySize, smem_gemm);
    dim3 gqkv(3 * D_ / 128, M_ / 128);   // (24, 256)
    gemm_ms<<<gqkv, 256, smem_gemm>>>((const __half*)pxs, (const __half*)pwqkv,
                                      (float*)pqk, (__half*)pvh, 1);

    // 3. tensor-core attention (emits fp16)
    cudaFuncSetAttribute(attn_tc, cudaFuncAttributeMaxDynamicSharedMemorySize, AT_SMEM);
    attn_tc<<<B_ * H_, 128, AT_SMEM>>>((const float*)pqk, (const __half*)pvh,
                                       bias, (__half*)pats);

    // 4. output projection
    dim3 go(D_ / 128, M_ / 128);   // (8, 256)
    gemm_ms<<<go, 256, smem_gemm>>>((const __half*)pats, (const __half*)pwo,
                                    out, (__half*)pvh, 0);
}